// round 3
// baseline (speedup 1.0000x reference)
#include <cuda_runtime.h>

#define BB   64
#define SS   512
#define KRAW 850
#define KPAD 864
#define HID  512
#define G4   2048
#define MTOT (BB * SS)

// ---------------- scratch (static device globals; no runtime alloc) ----------
__device__ float g_catL[(size_t)MTOT * KPAD];   // [32768, 864]
__device__ float g_catR[(size_t)MTOT * KPAD];
__device__ float g_Wpad[(size_t)HID * KPAD];    // W_lin zero-padded to K=864
__device__ float g_inL[(size_t)MTOT * HID];     // tanh(leftCat @ W_lin^T + b)
__device__ float g_inR[(size_t)MTOT * HID];
__device__ float g_xgL[(size_t)MTOT * G4];      // [S][B][2048] time-major gates
__device__ float g_xgR[(size_t)MTOT * G4];
__device__ float g_h[2][2][BB * HID];           // [dir][parity][B*H] double buffer
__device__ unsigned g_bar2[2];                  // per-direction grid barrier

__device__ __forceinline__ float sigf(float x) { return 1.f / (1.f + __expf(-x)); }

// ---------------- 1. gather + concat (padded) -------------------------------
__global__ void gather_kernel(const int* __restrict__ char_idx,
                              const int* __restrict__ ctype_idx,
                              const int* __restrict__ lbi_idx,
                              const int* __restrict__ rbi_idx,
                              const int* __restrict__ ext_idx,
                              const int* __restrict__ lext_idx,
                              const int* __restrict__ rext_idx,
                              const float* __restrict__ charEmb,
                              const float* __restrict__ ctypeEmb,
                              const float* __restrict__ biEmb,
                              const float* __restrict__ extEmb,
                              const float* __restrict__ extBiEmb)
{
    int t = blockIdx.x;                // token = b*S + s
    int tid = threadIdx.x;             // 128 threads
    float* L = g_catL + (size_t)t * KPAD;
    float* R = g_catR + (size_t)t * KPAD;

    int ci = char_idx[t];
    int ct = ctype_idx[t];
    int lb = lbi_idx[t];
    int rb = rbi_idx[t];
    int ec = ext_idx[t];
    int le = lext_idx[t];
    int re = rext_idx[t];

    const float4* c4  = (const float4*)(charEmb  + (size_t)ci * 200);
    const float4* e4  = (const float4*)(extEmb   + (size_t)ec * 200);
    const float4* lb4 = (const float4*)(biEmb    + (size_t)lb * 200);
    const float4* rb4 = (const float4*)(biEmb    + (size_t)rb * 200);
    const float4* le4 = (const float4*)(extBiEmb + (size_t)le * 200);
    const float4* re4 = (const float4*)(extBiEmb + (size_t)re * 200);

    for (int i = tid; i < 50; i += 128) {
        float4 v = c4[i];
        ((float4*)L)[i] = v;           ((float4*)R)[i] = v;
        v = e4[i];
        ((float4*)(L + 200))[i] = v;   ((float4*)(R + 200))[i] = v;
        ((float4*)(L + 400))[i] = lb4[i];
        ((float4*)(R + 400))[i] = rb4[i];
        ((float4*)(L + 600))[i] = le4[i];
        ((float4*)(R + 600))[i] = re4[i];
    }
    const float* cty = ctypeEmb + (size_t)ct * 50;
    for (int i = tid; i < KPAD - 800; i += 128) {
        float v = (i < 50) ? cty[i] : 0.f;
        L[800 + i] = v;
        R[800 + i] = v;
    }
}

// ---------------- 1b. pad W_lin ----------------------------------------------
__global__ void prep_w_kernel(const float* __restrict__ W_lin)
{
    int n = blockIdx.x;                // 512 rows
    const float* src = W_lin + (size_t)n * KRAW;
    float* dst = g_Wpad + (size_t)n * KPAD;
    for (int i = threadIdx.x; i < KPAD; i += blockDim.x)
        dst[i] = (i < KRAW) ? src[i] : 0.f;
}

// ---------------- 2. stage-1 GEMM: tanh(cat @ W_lin^T + b) -------------------
// C[32768,512], K = 864.  A and B both K-contiguous (C = A*B^T).
template <int SIDE>
__global__ __launch_bounds__(256, 2) void gemm1_kernel(const float* __restrict__ bias)
{
    const float* A = SIDE ? g_catR : g_catL;
    float*       C = SIDE ? g_inR  : g_inL;
    const float* Bw = g_Wpad;

    __shared__ float As[16][128 + 4];
    __shared__ float Bs[16][128 + 4];

    int tid = threadIdx.x;
    int tx = tid & 15, ty = tid >> 4;
    int m0 = blockIdx.y * 128, n0 = blockIdx.x * 128;

    float acc[8][8];
#pragma unroll
    for (int i = 0; i < 8; i++)
#pragma unroll
        for (int j = 0; j < 8; j++) acc[i][j] = 0.f;

    for (int k0 = 0; k0 < KPAD; k0 += 16) {
#pragma unroll
        for (int r = 0; r < 2; r++) {
            int id = tid + r * 256;
            int row = id >> 2, kg = (id & 3) << 2;
            float4 va = *(const float4*)&A[(size_t)(m0 + row) * KPAD + k0 + kg];
            As[kg + 0][row] = va.x; As[kg + 1][row] = va.y;
            As[kg + 2][row] = va.z; As[kg + 3][row] = va.w;
            float4 vb = *(const float4*)&Bw[(size_t)(n0 + row) * KPAD + k0 + kg];
            Bs[kg + 0][row] = vb.x; Bs[kg + 1][row] = vb.y;
            Bs[kg + 2][row] = vb.z; Bs[kg + 3][row] = vb.w;
        }
        __syncthreads();
#pragma unroll
        for (int k = 0; k < 16; k++) {
            float a[8], b[8];
            *(float4*)(a)     = *(const float4*)&As[k][ty * 8];
            *(float4*)(a + 4) = *(const float4*)&As[k][ty * 8 + 4];
            *(float4*)(b)     = *(const float4*)&Bs[k][tx * 8];
            *(float4*)(b + 4) = *(const float4*)&Bs[k][tx * 8 + 4];
#pragma unroll
            for (int i = 0; i < 8; i++)
#pragma unroll
                for (int j = 0; j < 8; j++) acc[i][j] += a[i] * b[j];
        }
        __syncthreads();
    }

    float bv[8];
#pragma unroll
    for (int j = 0; j < 8; j++) bv[j] = bias[n0 + tx * 8 + j];
#pragma unroll
    for (int i = 0; i < 8; i++) {
        int m = m0 + ty * 8 + i;
        float* crow = C + (size_t)m * HID + n0 + tx * 8;
        float4 v0, v1;
        v0.x = tanhf(acc[i][0] + bv[0]); v0.y = tanhf(acc[i][1] + bv[1]);
        v0.z = tanhf(acc[i][2] + bv[2]); v0.w = tanhf(acc[i][3] + bv[3]);
        v1.x = tanhf(acc[i][4] + bv[4]); v1.y = tanhf(acc[i][5] + bv[5]);
        v1.z = tanhf(acc[i][6] + bv[6]); v1.w = tanhf(acc[i][7] + bv[7]);
        ((float4*)crow)[0] = v0;
        ((float4*)crow)[1] = v1;
    }
}

// ---------------- 3. stage-2 GEMM: xg = in @ W_ih^T + b_ih + b_hh ------------
// scatter into [S][B][2048] layout (time-major for the recurrence).
template <int SIDE>
__global__ __launch_bounds__(256, 2) void gemm2_kernel(const float* __restrict__ W_ih,
                                                       const float* __restrict__ b_ih,
                                                       const float* __restrict__ b_hh)
{
    const float* A = SIDE ? g_inR : g_inL;
    float*       C = SIDE ? g_xgR : g_xgL;

    __shared__ float As[16][128 + 4];
    __shared__ float Bs[16][128 + 4];

    int tid = threadIdx.x;
    int tx = tid & 15, ty = tid >> 4;
    int m0 = blockIdx.y * 128, n0 = blockIdx.x * 128;

    float acc[8][8];
#pragma unroll
    for (int i = 0; i < 8; i++)
#pragma unroll
        for (int j = 0; j < 8; j++) acc[i][j] = 0.f;

    for (int k0 = 0; k0 < HID; k0 += 16) {
#pragma unroll
        for (int r = 0; r < 2; r++) {
            int id = tid + r * 256;
            int row = id >> 2, kg = (id & 3) << 2;
            float4 va = *(const float4*)&A[(size_t)(m0 + row) * HID + k0 + kg];
            As[kg + 0][row] = va.x; As[kg + 1][row] = va.y;
            As[kg + 2][row] = va.z; As[kg + 3][row] = va.w;
            float4 vb = *(const float4*)&W_ih[(size_t)(n0 + row) * HID + k0 + kg];
            Bs[kg + 0][row] = vb.x; Bs[kg + 1][row] = vb.y;
            Bs[kg + 2][row] = vb.z; Bs[kg + 3][row] = vb.w;
        }
        __syncthreads();
#pragma unroll
        for (int k = 0; k < 16; k++) {
            float a[8], b[8];
            *(float4*)(a)     = *(const float4*)&As[k][ty * 8];
            *(float4*)(a + 4) = *(const float4*)&As[k][ty * 8 + 4];
            *(float4*)(b)     = *(const float4*)&Bs[k][tx * 8];
            *(float4*)(b + 4) = *(const float4*)&Bs[k][tx * 8 + 4];
#pragma unroll
            for (int i = 0; i < 8; i++)
#pragma unroll
                for (int j = 0; j < 8; j++) acc[i][j] += a[i] * b[j];
        }
        __syncthreads();
    }

    float bv[8];
#pragma unroll
    for (int j = 0; j < 8; j++) {
        int n = n0 + tx * 8 + j;
        bv[j] = b_ih[n] + b_hh[n];
    }
#pragma unroll
    for (int i = 0; i < 8; i++) {
        int m = m0 + ty * 8 + i;      // token = b*S + s
        int s = m & (SS - 1);
        int b = m >> 9;
        float* crow = C + ((size_t)s * BB + b) * G4 + n0 + tx * 8;
        float4 v0, v1;
        v0.x = acc[i][0] + bv[0]; v0.y = acc[i][1] + bv[1];
        v0.z = acc[i][2] + bv[2]; v0.w = acc[i][3] + bv[3];
        v1.x = acc[i][4] + bv[4]; v1.y = acc[i][5] + bv[5];
        v1.z = acc[i][6] + bv[6]; v1.w = acc[i][7] + bv[7];
        ((float4*)crow)[0] = v0;
        ((float4*)crow)[1] = v1;
    }
}

// ---------------- 4. reset LSTM state ----------------------------------------
__global__ void init_kernel()
{
    int i = blockIdx.x * blockDim.x + threadIdx.x;
    if (i == 0) { g_bar2[0] = 0u; g_bar2[1] = 0u; }
    float* h = &g_h[0][0][0];
    int n = 2 * 2 * BB * HID;
    for (int j = i; j < n; j += gridDim.x * blockDim.x) h[j] = 0.f;
}

// ---------------- 5. persistent bidirectional LSTM ---------------------------
// 128 CTAs: dir = bid>>6 (64 CTAs/direction), each CTA owns 8 hidden units
// (32 gate columns).  W_hh slice lives k-major in SMEM; c-state in SMEM.
// Threads: (mi 0..15)x(ci 0..7)x(kh 0..1) -> 4m x 4c outputs over half of K.
__global__ __launch_bounds__(256, 1) void lstm_kernel(const float* __restrict__ Whl,
                                                      const float* __restrict__ Whr,
                                                      float* __restrict__ out)
{
    extern __shared__ float sm[];
    float* Ws  = sm;                    // [512][32]  (k-major W slice)  16384
    float* Hs  = sm + 512 * 32;         // [128][68]  h chunk, transposed 8704
    float* Gm  = Hs + 128 * 68;         // [64][33]   gate matrix        2112
    float* Cst = Gm + 64 * 33;          // [512]      cell state
    float* Redu = Hs;                   // aliases Hs (free at reduce time)

    int tid = threadIdx.x;
    int bid = blockIdx.x;
    int dir = bid >> 6;
    int n0  = (bid & 63) << 3;          // first hidden unit of this CTA

    const float* Whh = dir ? Whr : Whl;
    const float* xg  = dir ? g_xgR : g_xgL;
    float* hb0 = g_h[dir][0];
    float* hb1 = g_h[dir][1];

    // Load W slice transposed: Ws[k*32 + c] = Whh[gate_row(c)][k]
    for (int id = tid; id < 512 * 32; id += 256) {
        int c = id & 31, k = id >> 5;
        int row = ((c >> 3) << 9) + n0 + (c & 7);
        Ws[id] = Whh[(size_t)row * 512 + k];
    }
    for (int i = tid; i < 512; i += 256) Cst[i] = 0.f;
    __syncthreads();

    int mi = tid & 15;
    int ci = (tid >> 4) & 7;
    int kh = tid >> 7;
    int mbase = mi << 2;
    int cbase = ci << 2;

    for (int it = 0; it < SS; it++) {
        int t = dir ? (SS - 1 - it) : it;
        const float* hprev = (it & 1) ? hb1 : hb0;
        float*       hnext = (it & 1) ? hb0 : hb1;

        float acc[4][4];
#pragma unroll
        for (int a = 0; a < 4; a++)
#pragma unroll
            for (int b = 0; b < 4; b++) acc[a][b] = 0.f;

        for (int kc = 0; kc < 512; kc += 128) {
            // stage h chunk (transposed), bypassing L1 (cross-CTA producer)
            for (int id = tid; id < 2048; id += 256) {
                int m = id >> 5, kq = id & 31;
                float4 v = __ldcg((const float4*)&hprev[m * 512 + kc + (kq << 2)]);
                int kk = kq << 2;
                Hs[(kk + 0) * 68 + m] = v.x;
                Hs[(kk + 1) * 68 + m] = v.y;
                Hs[(kk + 2) * 68 + m] = v.z;
                Hs[(kk + 3) * 68 + m] = v.w;
            }
            __syncthreads();
            const float* wp = Ws + (size_t)(kc + (kh << 6)) * 32 + cbase;
            const float* hp = Hs + (size_t)(kh << 6) * 68 + mbase;
#pragma unroll 8
            for (int k = 0; k < 64; k++) {
                float4 h4 = *(const float4*)(hp + k * 68);
                float4 w4 = *(const float4*)(wp + k * 32);
                acc[0][0] += h4.x * w4.x; acc[0][1] += h4.x * w4.y;
                acc[0][2] += h4.x * w4.z; acc[0][3] += h4.x * w4.w;
                acc[1][0] += h4.y * w4.x; acc[1][1] += h4.y * w4.y;
                acc[1][2] += h4.y * w4.z; acc[1][3] += h4.y * w4.w;
                acc[2][0] += h4.z * w4.x; acc[2][1] += h4.z * w4.y;
                acc[2][2] += h4.z * w4.z; acc[2][3] += h4.z * w4.w;
                acc[3][0] += h4.w * w4.x; acc[3][1] += h4.w * w4.y;
                acc[3][2] += h4.w * w4.z; acc[3][3] += h4.w * w4.w;
            }
            __syncthreads();
        }

        // reduce the two K-halves
        int slot = ((mi << 3) + ci) * 17;   // pad-17 -> conflict-free
        if (kh) {
#pragma unroll
            for (int a = 0; a < 4; a++)
#pragma unroll
                for (int b = 0; b < 4; b++) Redu[slot + a * 4 + b] = acc[a][b];
        }
        __syncthreads();
        if (!kh) {
#pragma unroll
            for (int a = 0; a < 4; a++)
#pragma unroll
                for (int b = 0; b < 4; b++) {
                    float v = acc[a][b] + Redu[slot + a * 4 + b];
                    Gm[(mbase + a) * 33 + cbase + b] = v;
                }
        }
        __syncthreads();

        // elementwise LSTM update for (m, unit j)
        size_t xb = (size_t)t * (BB * G4);
        for (int item = tid; item < 512; item += 256) {
            int m = item >> 3, j = item & 7;
            const float* xr = xg + xb + m * G4 + n0 + j;
            float gi = Gm[m * 33 + j]      + xr[0];
            float gf = Gm[m * 33 + 8 + j]  + xr[512];
            float gg = Gm[m * 33 + 16 + j] + xr[1024];
            float go = Gm[m * 33 + 24 + j] + xr[1536];
            float co = Cst[item];
            float cn = sigf(gf) * co + sigf(gi) * tanhf(gg);
            float h  = sigf(go) * tanhf(cn);
            Cst[item] = cn;
            hnext[m * 512 + n0 + j] = h;
            out[((size_t)m * SS + t) * 1024 + (dir << 9) + n0 + j] = h;
        }

        // per-direction grid barrier (all 64 CTAs co-resident by construction)
        if (it != SS - 1) {
            __syncthreads();
            __threadfence();
            if (tid == 0) {
                atomicAdd(&g_bar2[dir], 1u);
                unsigned tgt = (unsigned)(it + 1) * 64u;
                while (*(volatile unsigned*)&g_bar2[dir] < tgt) __nanosleep(32);
            }
            __syncthreads();
        }
    }
}

// ---------------- host launch -------------------------------------------------
extern "C" void kernel_launch(void* const* d_in, const int* in_sizes, int n_in,
                              void* d_out, int out_size)
{
    const int*   char_idx  = (const int*)d_in[0];
    const int*   ctype_idx = (const int*)d_in[1];
    const int*   lbi_idx   = (const int*)d_in[2];
    const int*   rbi_idx   = (const int*)d_in[3];
    const int*   ext_idx   = (const int*)d_in[4];
    const int*   lext_idx  = (const int*)d_in[5];
    const int*   rext_idx  = (const int*)d_in[6];
    const float* charEmb   = (const float*)d_in[7];
    const float* ctypeEmb  = (const float*)d_in[8];
    const float* biEmb     = (const float*)d_in[9];
    const float* extEmb    = (const float*)d_in[10];
    const float* extBiEmb  = (const float*)d_in[11];
    const float* W_lin     = (const float*)d_in[12];
    const float* b_lin     = (const float*)d_in[13];
    const float* W_ih_l    = (const float*)d_in[14];
    const float* W_hh_l    = (const float*)d_in[15];
    const float* b_ih_l    = (const float*)d_in[16];
    const float* b_hh_l    = (const float*)d_in[17];
    const float* W_ih_r    = (const float*)d_in[18];
    const float* W_hh_r    = (const float*)d_in[19];
    const float* b_ih_r    = (const float*)d_in[20];
    const float* b_hh_r    = (const float*)d_in[21];
    float* out = (float*)d_out;

    gather_kernel<<<MTOT, 128>>>(char_idx, ctype_idx, lbi_idx, rbi_idx,
                                 ext_idx, lext_idx, rext_idx,
                                 charEmb, ctypeEmb, biEmb, extEmb, extBiEmb);
    prep_w_kernel<<<512, 128>>>(W_lin);

    gemm1_kernel<0><<<dim3(4, 256), 256>>>(b_lin);
    gemm1_kernel<1><<<dim3(4, 256), 256>>>(b_lin);
    gemm2_kernel<0><<<dim3(16, 256), 256>>>(W_ih_l, b_ih_l, b_hh_l);
    gemm2_kernel<1><<<dim3(16, 256), 256>>>(W_ih_r, b_ih_r, b_hh_r);

    init_kernel<<<64, 256>>>();

    const int lstm_smem = (512 * 32 + 128 * 68 + 64 * 33 + 512) * 4;  // 110848 B
    cudaFuncSetAttribute(lstm_kernel, cudaFuncAttributeMaxDynamicSharedMemorySize,
                         lstm_smem);
    lstm_kernel<<<128, 256, lstm_smem>>>(W_hh_l, W_hh_r, out);
}

// round 4
// speedup vs baseline: 1.8710x; 1.8710x over previous
#include <cuda_runtime.h>

#define BB   64
#define SS   512
#define KRAW 850
#define KPAD 864
#define HID  512
#define G4   2048
#define MTOT (BB * SS)

// ---------------- scratch (static device globals; no runtime alloc) ----------
__device__ float g_catL[(size_t)MTOT * KPAD];   // [32768, 864]
__device__ float g_catR[(size_t)MTOT * KPAD];
__device__ float g_Wpad[(size_t)HID * KPAD];    // W_lin zero-padded to K=864
__device__ float g_inL[(size_t)MTOT * HID];     // tanh(leftCat @ W_lin^T + b)
__device__ float g_inR[(size_t)MTOT * HID];
__device__ float g_xgL[(size_t)MTOT * G4];      // [S][B][2048] time-major gates
__device__ float g_xgR[(size_t)MTOT * G4];
// h double buffer, stored in mma A-fragment-packed layout (tf32-rounded):
// idx = ((ki*4 + mt)*32 + lane)*4 + e   where ki=k>>3, mt=m>>4,
// lane=(m&7)*4+(k&3), e=((m>>3)&1) + 2*((k>>2)&1)
__device__ __align__(16) float g_h[2][2][BB * HID];
__device__ unsigned g_bar2[2];                  // per-direction grid barrier

__device__ __forceinline__ float sigf(float x) { return 1.f / (1.f + __expf(-x)); }
__device__ __forceinline__ float to_tf32(float x) {
    float r;
    asm("cvt.rna.tf32.f32 %0, %1;" : "=f"(r) : "f"(x));
    return r;
}

// ---------------- 1. gather + concat (padded) -------------------------------
__global__ void gather_kernel(const int* __restrict__ char_idx,
                              const int* __restrict__ ctype_idx,
                              const int* __restrict__ lbi_idx,
                              const int* __restrict__ rbi_idx,
                              const int* __restrict__ ext_idx,
                              const int* __restrict__ lext_idx,
                              const int* __restrict__ rext_idx,
                              const float* __restrict__ charEmb,
                              const float* __restrict__ ctypeEmb,
                              const float* __restrict__ biEmb,
                              const float* __restrict__ extEmb,
                              const float* __restrict__ extBiEmb)
{
    int t = blockIdx.x;                // token = b*S + s
    int tid = threadIdx.x;             // 128 threads
    float* L = g_catL + (size_t)t * KPAD;
    float* R = g_catR + (size_t)t * KPAD;

    int ci = char_idx[t];
    int ct = ctype_idx[t];
    int lb = lbi_idx[t];
    int rb = rbi_idx[t];
    int ec = ext_idx[t];
    int le = lext_idx[t];
    int re = rext_idx[t];

    const float4* c4  = (const float4*)(charEmb  + (size_t)ci * 200);
    const float4* e4  = (const float4*)(extEmb   + (size_t)ec * 200);
    const float4* lb4 = (const float4*)(biEmb    + (size_t)lb * 200);
    const float4* rb4 = (const float4*)(biEmb    + (size_t)rb * 200);
    const float4* le4 = (const float4*)(extBiEmb + (size_t)le * 200);
    const float4* re4 = (const float4*)(extBiEmb + (size_t)re * 200);

    for (int i = tid; i < 50; i += 128) {
        float4 v = c4[i];
        ((float4*)L)[i] = v;           ((float4*)R)[i] = v;
        v = e4[i];
        ((float4*)(L + 200))[i] = v;   ((float4*)(R + 200))[i] = v;
        ((float4*)(L + 400))[i] = lb4[i];
        ((float4*)(R + 400))[i] = rb4[i];
        ((float4*)(L + 600))[i] = le4[i];
        ((float4*)(R + 600))[i] = re4[i];
    }
    const float* cty = ctypeEmb + (size_t)ct * 50;
    for (int i = tid; i < KPAD - 800; i += 128) {
        float v = (i < 50) ? cty[i] : 0.f;
        L[800 + i] = v;
        R[800 + i] = v;
    }
}

// ---------------- 1b. pad W_lin ----------------------------------------------
__global__ void prep_w_kernel(const float* __restrict__ W_lin)
{
    int n = blockIdx.x;                // 512 rows
    const float* src = W_lin + (size_t)n * KRAW;
    float* dst = g_Wpad + (size_t)n * KPAD;
    for (int i = threadIdx.x; i < KPAD; i += blockDim.x)
        dst[i] = (i < KRAW) ? src[i] : 0.f;
}

// ---------------- 2. stage-1 GEMM: tanh(cat @ W_lin^T + b) -------------------
template <int SIDE>
__global__ __launch_bounds__(256, 2) void gemm1_kernel(const float* __restrict__ bias)
{
    const float* A = SIDE ? g_catR : g_catL;
    float*       C = SIDE ? g_inR  : g_inL;
    const float* Bw = g_Wpad;

    __shared__ float As[16][128 + 4];
    __shared__ float Bs[16][128 + 4];

    int tid = threadIdx.x;
    int tx = tid & 15, ty = tid >> 4;
    int m0 = blockIdx.y * 128, n0 = blockIdx.x * 128;

    float acc[8][8];
#pragma unroll
    for (int i = 0; i < 8; i++)
#pragma unroll
        for (int j = 0; j < 8; j++) acc[i][j] = 0.f;

    for (int k0 = 0; k0 < KPAD; k0 += 16) {
#pragma unroll
        for (int r = 0; r < 2; r++) {
            int id = tid + r * 256;
            int row = id >> 2, kg = (id & 3) << 2;
            float4 va = *(const float4*)&A[(size_t)(m0 + row) * KPAD + k0 + kg];
            As[kg + 0][row] = va.x; As[kg + 1][row] = va.y;
            As[kg + 2][row] = va.z; As[kg + 3][row] = va.w;
            float4 vb = *(const float4*)&Bw[(size_t)(n0 + row) * KPAD + k0 + kg];
            Bs[kg + 0][row] = vb.x; Bs[kg + 1][row] = vb.y;
            Bs[kg + 2][row] = vb.z; Bs[kg + 3][row] = vb.w;
        }
        __syncthreads();
#pragma unroll
        for (int k = 0; k < 16; k++) {
            float a[8], b[8];
            *(float4*)(a)     = *(const float4*)&As[k][ty * 8];
            *(float4*)(a + 4) = *(const float4*)&As[k][ty * 8 + 4];
            *(float4*)(b)     = *(const float4*)&Bs[k][tx * 8];
            *(float4*)(b + 4) = *(const float4*)&Bs[k][tx * 8 + 4];
#pragma unroll
            for (int i = 0; i < 8; i++)
#pragma unroll
                for (int j = 0; j < 8; j++) acc[i][j] += a[i] * b[j];
        }
        __syncthreads();
    }

    float bv[8];
#pragma unroll
    for (int j = 0; j < 8; j++) bv[j] = bias[n0 + tx * 8 + j];
#pragma unroll
    for (int i = 0; i < 8; i++) {
        int m = m0 + ty * 8 + i;
        float* crow = C + (size_t)m * HID + n0 + tx * 8;
        float4 v0, v1;
        v0.x = tanhf(acc[i][0] + bv[0]); v0.y = tanhf(acc[i][1] + bv[1]);
        v0.z = tanhf(acc[i][2] + bv[2]); v0.w = tanhf(acc[i][3] + bv[3]);
        v1.x = tanhf(acc[i][4] + bv[4]); v1.y = tanhf(acc[i][5] + bv[5]);
        v1.z = tanhf(acc[i][6] + bv[6]); v1.w = tanhf(acc[i][7] + bv[7]);
        ((float4*)crow)[0] = v0;
        ((float4*)crow)[1] = v1;
    }
}

// ---------------- 3. stage-2 GEMM: xg = in @ W_ih^T + b_ih + b_hh ------------
template <int SIDE>
__global__ __launch_bounds__(256, 2) void gemm2_kernel(const float* __restrict__ W_ih,
                                                       const float* __restrict__ b_ih,
                                                       const float* __restrict__ b_hh)
{
    const float* A = SIDE ? g_inR : g_inL;
    float*       C = SIDE ? g_xgR : g_xgL;

    __shared__ float As[16][128 + 4];
    __shared__ float Bs[16][128 + 4];

    int tid = threadIdx.x;
    int tx = tid & 15, ty = tid >> 4;
    int m0 = blockIdx.y * 128, n0 = blockIdx.x * 128;

    float acc[8][8];
#pragma unroll
    for (int i = 0; i < 8; i++)
#pragma unroll
        for (int j = 0; j < 8; j++) acc[i][j] = 0.f;

    for (int k0 = 0; k0 < HID; k0 += 16) {
#pragma unroll
        for (int r = 0; r < 2; r++) {
            int id = tid + r * 256;
            int row = id >> 2, kg = (id & 3) << 2;
            float4 va = *(const float4*)&A[(size_t)(m0 + row) * HID + k0 + kg];
            As[kg + 0][row] = va.x; As[kg + 1][row] = va.y;
            As[kg + 2][row] = va.z; As[kg + 3][row] = va.w;
            float4 vb = *(const float4*)&W_ih[(size_t)(n0 + row) * HID + k0 + kg];
            Bs[kg + 0][row] = vb.x; Bs[kg + 1][row] = vb.y;
            Bs[kg + 2][row] = vb.z; Bs[kg + 3][row] = vb.w;
        }
        __syncthreads();
#pragma unroll
        for (int k = 0; k < 16; k++) {
            float a[8], b[8];
            *(float4*)(a)     = *(const float4*)&As[k][ty * 8];
            *(float4*)(a + 4) = *(const float4*)&As[k][ty * 8 + 4];
            *(float4*)(b)     = *(const float4*)&Bs[k][tx * 8];
            *(float4*)(b + 4) = *(const float4*)&Bs[k][tx * 8 + 4];
#pragma unroll
            for (int i = 0; i < 8; i++)
#pragma unroll
                for (int j = 0; j < 8; j++) acc[i][j] += a[i] * b[j];
        }
        __syncthreads();
    }

    float bv[8];
#pragma unroll
    for (int j = 0; j < 8; j++) {
        int n = n0 + tx * 8 + j;
        bv[j] = b_ih[n] + b_hh[n];
    }
#pragma unroll
    for (int i = 0; i < 8; i++) {
        int m = m0 + ty * 8 + i;      // token = b*S + s
        int s = m & (SS - 1);
        int b = m >> 9;
        float* crow = C + ((size_t)s * BB + b) * G4 + n0 + tx * 8;
        float4 v0, v1;
        v0.x = acc[i][0] + bv[0]; v0.y = acc[i][1] + bv[1];
        v0.z = acc[i][2] + bv[2]; v0.w = acc[i][3] + bv[3];
        v1.x = acc[i][4] + bv[4]; v1.y = acc[i][5] + bv[5];
        v1.z = acc[i][6] + bv[6]; v1.w = acc[i][7] + bv[7];
        ((float4*)crow)[0] = v0;
        ((float4*)crow)[1] = v1;
    }
}

// ---------------- 4. reset LSTM state ----------------------------------------
__global__ void init_kernel()
{
    int i = blockIdx.x * blockDim.x + threadIdx.x;
    if (i == 0) { g_bar2[0] = 0u; g_bar2[1] = 0u; }
    float* h = &g_h[0][0][0];
    int n = 2 * 2 * BB * HID;
    for (int j = i; j < n; j += gridDim.x * blockDim.x) h[j] = 0.f;
}

// ---------------- 5. persistent bidirectional LSTM (tf32 tensor cores) -------
// 128 CTAs: dir = bid>>6, each CTA owns 8 hidden units (32 gate columns).
// Per step: h [64,512] @ Wslice [512,32] via mma.sync.m16n8k8.tf32.
// W pre-packed in SMEM as B fragments; h staged in SMEM already in A-fragment
// layout (producers write packed).  8 warps = (kq 0..3 K-split) x (mh 0..1),
// each warp: 2 m-tiles x 4 n-tiles x 16 k-iters.
#define SM_WF   0                       // 16384 floats (W fragments)
#define SM_AF   16384                   // 32768 floats (A fragments / aliased Pb)
#define SM_CST  49152                   // 512 floats (cell state)
#define SM_TOT  49664                   // floats

__global__ __launch_bounds__(256, 1) void lstm_kernel(const float* __restrict__ Whl,
                                                      const float* __restrict__ Whr,
                                                      float* __restrict__ out)
{
    extern __shared__ float sm[];
    float* Wf  = sm + SM_WF;
    float* Af  = sm + SM_AF;
    float* Pb  = sm + SM_AF;            // aliases Af (used after mma phase)
    float* Cst = sm + SM_CST;

    int tid = threadIdx.x;
    int bid = blockIdx.x;
    int dir = bid >> 6;
    int n0  = (bid & 63) << 3;          // first hidden unit of this CTA

    const float* Whh = dir ? Whr : Whl;
    const float* xg  = dir ? g_xgR : g_xgL;
    float* hb0 = g_h[dir][0];
    float* hb1 = g_h[dir][1];

    // ---- pack W slice into B-fragment layout (tf32-rounded), once ----------
    // Wf[((ki*4+nt)*32+lane)*2+e] = Whh[grow][k], k = ki*8 + e*4 + (lane&3),
    // c = nt*8 + (lane>>2), grow = (c>>3)*512 + n0 + (c&7)
    for (int id = tid; id < 16384; id += 256) {
        int e    = id & 1;
        int lane = (id >> 1) & 31;
        int nt   = (id >> 6) & 3;
        int ki   = id >> 8;
        int k    = ki * 8 + e * 4 + (lane & 3);
        int c    = nt * 8 + (lane >> 2);
        int grow = ((c >> 3) << 9) + n0 + (c & 7);
        Wf[id] = to_tf32(Whh[(size_t)grow * 512 + k]);
    }
    for (int i = tid; i < 512; i += 256) Cst[i] = 0.f;
    __syncthreads();

    int lane = tid & 31;
    int w    = tid >> 5;
    int kq   = w >> 1;                  // 0..3 : K range [kq*128, +128)
    int mh   = w & 1;                   // m-tiles {mh*2, mh*2+1}

    for (int it = 0; it < SS; it++) {
        int t = dir ? (SS - 1 - it) : it;
        const float* hprev = (it & 1) ? hb1 : hb0;
        float*       hnext = (it & 1) ? hb0 : hb1;

        // ---- stage full h (already fragment-packed) into SMEM --------------
        for (int i = tid; i < 8192; i += 256) {
            float4 v = __ldcg((const float4*)hprev + i);
            ((float4*)Af)[i] = v;
        }
        __syncthreads();

        // ---- tensor mma phase ----------------------------------------------
        float acc[2][4][4];
#pragma unroll
        for (int mi = 0; mi < 2; mi++)
#pragma unroll
            for (int nt = 0; nt < 4; nt++)
#pragma unroll
                for (int r = 0; r < 4; r++) acc[mi][nt][r] = 0.f;

#pragma unroll 4
        for (int kl = 0; kl < 16; kl++) {
            int ki = kq * 16 + kl;
            uint4 a[2];
#pragma unroll
            for (int mi = 0; mi < 2; mi++) {
                int mt = mh * 2 + mi;
                a[mi] = *(const uint4*)&Af[((ki * 4 + mt) * 32 + lane) * 4];
            }
#pragma unroll
            for (int nt = 0; nt < 4; nt++) {
                uint2 b = *(const uint2*)&Wf[((ki * 4 + nt) * 32 + lane) * 2];
#pragma unroll
                for (int mi = 0; mi < 2; mi++) {
                    asm volatile(
                        "mma.sync.aligned.m16n8k8.row.col.f32.tf32.tf32.f32 "
                        "{%0,%1,%2,%3}, {%4,%5,%6,%7}, {%8,%9}, {%0,%1,%2,%3};"
                        : "+f"(acc[mi][nt][0]), "+f"(acc[mi][nt][1]),
                          "+f"(acc[mi][nt][2]), "+f"(acc[mi][nt][3])
                        : "r"(a[mi].x), "r"(a[mi].y), "r"(a[mi].z), "r"(a[mi].w),
                          "r"(b.x), "r"(b.y));
                }
            }
        }
        __syncthreads();   // all warps done reading Af before Pb overwrites it

        // ---- store K-partials to SMEM (Pb aliases Af) ----------------------
        // elem (r, c): lane = (r&7)*4 + (c>>1), reg = ((r>>3)&1)*2 + (c&1)
#pragma unroll
        for (int mi = 0; mi < 2; mi++) {
            int mt = mh * 2 + mi;
#pragma unroll
            for (int nt = 0; nt < 4; nt++) {
#pragma unroll
                for (int r = 0; r < 4; r++) {
                    int row = mt * 16 + (lane >> 2) + ((r >> 1) << 3);
                    int col = nt * 8 + (lane & 3) * 2 + (r & 1);
                    Pb[(kq * 64 + row) * 33 + col] = acc[mi][nt][r];
                }
            }
        }
        __syncthreads();

        // ---- gate reduction + elementwise LSTM update ----------------------
        size_t xb = (size_t)t * (BB * G4);
        for (int item = tid; item < 512; item += 256) {
            int m = item >> 3, j = item & 7;
            const float* xr = xg + xb + m * G4 + n0 + j;
            float gi = xr[0],    gf = xr[512];
            float gg = xr[1024], go = xr[1536];
#pragma unroll
            for (int q = 0; q < 4; q++) {
                const float* p = &Pb[(q * 64 + m) * 33];
                gi += p[j];      gf += p[8 + j];
                gg += p[16 + j]; go += p[24 + j];
            }
            float co = Cst[item];
            float cn = sigf(gf) * co + sigf(gi) * tanhf(gg);
            float h  = sigf(go) * tanhf(cn);
            Cst[item] = cn;

            // write h into fragment-packed global layout (tf32-rounded)
            int kglob = n0 + j;
            int ki2 = kglob >> 3, kc = kglob & 7;
            int mt2 = m >> 4, mr = m & 15;
            int ln  = (mr & 7) * 4 + (kc & 3);
            int e   = ((mr >> 3) & 1) + 2 * ((kc >> 2) & 1);
            hnext[((ki2 * 4 + mt2) * 32 + ln) * 4 + e] = to_tf32(h);

            out[((size_t)m * SS + t) * 1024 + (dir << 9) + n0 + j] = h;
        }

        // ---- per-direction grid barrier ------------------------------------
        if (it != SS - 1) {
            __syncthreads();
            __threadfence();
            if (tid == 0) {
                atomicAdd(&g_bar2[dir], 1u);
                unsigned tgt = (unsigned)(it + 1) * 64u;
                while (*(volatile unsigned*)&g_bar2[dir] < tgt) __nanosleep(32);
            }
            __syncthreads();
        }
    }
}

// ---------------- host launch -------------------------------------------------
extern "C" void kernel_launch(void* const* d_in, const int* in_sizes, int n_in,
                              void* d_out, int out_size)
{
    const int*   char_idx  = (const int*)d_in[0];
    const int*   ctype_idx = (const int*)d_in[1];
    const int*   lbi_idx   = (const int*)d_in[2];
    const int*   rbi_idx   = (const int*)d_in[3];
    const int*   ext_idx   = (const int*)d_in[4];
    const int*   lext_idx  = (const int*)d_in[5];
    const int*   rext_idx  = (const int*)d_in[6];
    const float* charEmb   = (const float*)d_in[7];
    const float* ctypeEmb  = (const float*)d_in[8];
    const float* biEmb     = (const float*)d_in[9];
    const float* extEmb    = (const float*)d_in[10];
    const float* extBiEmb  = (const float*)d_in[11];
    const float* W_lin     = (const float*)d_in[12];
    const float* b_lin     = (const float*)d_in[13];
    const float* W_ih_l    = (const float*)d_in[14];
    const float* W_hh_l    = (const float*)d_in[15];
    const float* b_ih_l    = (const float*)d_in[16];
    const float* b_hh_l    = (const float*)d_in[17];
    const float* W_ih_r    = (const float*)d_in[18];
    const float* W_hh_r    = (const float*)d_in[19];
    const float* b_ih_r    = (const float*)d_in[20];
    const float* b_hh_r    = (const float*)d_in[21];
    float* out = (float*)d_out;

    gather_kernel<<<MTOT, 128>>>(char_idx, ctype_idx, lbi_idx, rbi_idx,
                                 ext_idx, lext_idx, rext_idx,
                                 charEmb, ctypeEmb, biEmb, extEmb, extBiEmb);
    prep_w_kernel<<<512, 128>>>(W_lin);

    gemm1_kernel<0><<<dim3(4, 256), 256>>>(b_lin);
    gemm1_kernel<1><<<dim3(4, 256), 256>>>(b_lin);
    gemm2_kernel<0><<<dim3(16, 256), 256>>>(W_ih_l, b_ih_l, b_hh_l);
    gemm2_kernel<1><<<dim3(16, 256), 256>>>(W_ih_r, b_ih_r, b_hh_r);

    init_kernel<<<64, 256>>>();

    const int lstm_smem = SM_TOT * 4;   // 198656 B
    cudaFuncSetAttribute(lstm_kernel, cudaFuncAttributeMaxDynamicSharedMemorySize,
                         lstm_smem);
    lstm_kernel<<<128, 256, lstm_smem>>>(W_hh_l, W_hh_r, out);
}

// round 5
// speedup vs baseline: 2.4473x; 1.3080x over previous
#include <cuda_runtime.h>

#define BB   64
#define SS   512
#define KRAW 850
#define KPAD 864
#define HID  512
#define G4   2048
#define MTOT (BB * SS)

// ---------------- scratch (static device globals; no runtime alloc) ----------
__device__ __align__(16) float g_catL[(size_t)MTOT * KPAD];
__device__ __align__(16) float g_catR[(size_t)MTOT * KPAD];
__device__ __align__(16) float g_Wpad[(size_t)HID * KPAD];
__device__ __align__(16) float g_WihL[(size_t)G4 * HID];   // tf32-rounded W_ih
__device__ __align__(16) float g_WihR[(size_t)G4 * HID];
__device__ __align__(16) float g_inL[(size_t)MTOT * HID];
__device__ __align__(16) float g_inR[(size_t)MTOT * HID];
__device__ __align__(16) float g_xgL[(size_t)MTOT * G4];   // [S][B][2048]
__device__ __align__(16) float g_xgR[(size_t)MTOT * G4];
// h double buffer, mma-A-fragment-packed (tf32):
// idx = ((ki*4+mt)*32+lane)*4+e, ki=k>>3, mt=m>>4, lane=(m&7)*4+(k&3),
// e = ((m>>3)&1) + 2*((k>>2)&1)
__device__ __align__(16) float g_h[2][2][BB * HID];
__device__ unsigned g_bar2[2];

__device__ __forceinline__ float sigf(float x) { return 1.f / (1.f + __expf(-x)); }
__device__ __forceinline__ float to_tf32(float x) {
    float r;
    asm("cvt.rna.tf32.f32 %0, %1;" : "=f"(r) : "f"(x));
    return r;
}
__device__ __forceinline__ float4 t4(float4 v) {
    v.x = to_tf32(v.x); v.y = to_tf32(v.y);
    v.z = to_tf32(v.z); v.w = to_tf32(v.w);
    return v;
}
__device__ __forceinline__ void mma_tf32(float* c, const float4& a, const float2& b) {
    asm volatile(
        "mma.sync.aligned.m16n8k8.row.col.f32.tf32.tf32.f32 "
        "{%0,%1,%2,%3}, {%4,%5,%6,%7}, {%8,%9}, {%0,%1,%2,%3};"
        : "+f"(c[0]), "+f"(c[1]), "+f"(c[2]), "+f"(c[3])
        : "r"(__float_as_uint(a.x)), "r"(__float_as_uint(a.y)),
          "r"(__float_as_uint(a.z)), "r"(__float_as_uint(a.w)),
          "r"(__float_as_uint(b.x)), "r"(__float_as_uint(b.y)));
}
__device__ __forceinline__ void cp16(float* smem, const float* gmem) {
    unsigned s = (unsigned)__cvta_generic_to_shared(smem);
    asm volatile("cp.async.cg.shared.global [%0], [%1], 16;\n" :: "r"(s), "l"(gmem));
}

// ---------------- 1. gather + concat (padded, tf32-rounded) ------------------
__global__ void gather_kernel(const int* __restrict__ char_idx,
                              const int* __restrict__ ctype_idx,
                              const int* __restrict__ lbi_idx,
                              const int* __restrict__ rbi_idx,
                              const int* __restrict__ ext_idx,
                              const int* __restrict__ lext_idx,
                              const int* __restrict__ rext_idx,
                              const float* __restrict__ charEmb,
                              const float* __restrict__ ctypeEmb,
                              const float* __restrict__ biEmb,
                              const float* __restrict__ extEmb,
                              const float* __restrict__ extBiEmb)
{
    int t = blockIdx.x;
    int tid = threadIdx.x;             // 128 threads
    float* L = g_catL + (size_t)t * KPAD;
    float* R = g_catR + (size_t)t * KPAD;

    int ci = char_idx[t];
    int ct = ctype_idx[t];
    int lb = lbi_idx[t];
    int rb = rbi_idx[t];
    int ec = ext_idx[t];
    int le = lext_idx[t];
    int re = rext_idx[t];

    const float4* c4  = (const float4*)(charEmb  + (size_t)ci * 200);
    const float4* e4  = (const float4*)(extEmb   + (size_t)ec * 200);
    const float4* lb4 = (const float4*)(biEmb    + (size_t)lb * 200);
    const float4* rb4 = (const float4*)(biEmb    + (size_t)rb * 200);
    const float4* le4 = (const float4*)(extBiEmb + (size_t)le * 200);
    const float4* re4 = (const float4*)(extBiEmb + (size_t)re * 200);

    for (int i = tid; i < 50; i += 128) {
        float4 v = t4(c4[i]);
        ((float4*)L)[i] = v;           ((float4*)R)[i] = v;
        v = t4(e4[i]);
        ((float4*)(L + 200))[i] = v;   ((float4*)(R + 200))[i] = v;
        ((float4*)(L + 400))[i] = t4(lb4[i]);
        ((float4*)(R + 400))[i] = t4(rb4[i]);
        ((float4*)(L + 600))[i] = t4(le4[i]);
        ((float4*)(R + 600))[i] = t4(re4[i]);
    }
    const float* cty = ctypeEmb + (size_t)ct * 50;
    for (int i = tid; i < KPAD - 800; i += 128) {
        float v = (i < 50) ? to_tf32(cty[i]) : 0.f;
        L[800 + i] = v;
        R[800 + i] = v;
    }
}

// ---------------- 1b. weight prep (pad + tf32 round) -------------------------
__global__ void prep_w_kernel(const float* __restrict__ W_lin)
{
    int n = blockIdx.x;
    const float* src = W_lin + (size_t)n * KRAW;
    float* dst = g_Wpad + (size_t)n * KPAD;
    for (int i = threadIdx.x; i < KPAD; i += blockDim.x)
        dst[i] = (i < KRAW) ? to_tf32(src[i]) : 0.f;
}

__global__ void prep_wih_kernel(const float* __restrict__ Wl,
                                const float* __restrict__ Wr)
{
    int i = blockIdx.x * blockDim.x + threadIdx.x;
    int n = G4 * HID;
    for (int j = i; j < n; j += gridDim.x * blockDim.x) {
        g_WihL[j] = to_tf32(Wl[j]);
        g_WihR[j] = to_tf32(Wr[j]);
    }
}

// ---------------- 2. stage-1 tensor GEMM: tanh(cat @ W_lin^T + b) ------------
// C[32768,512], K=864.  128x128 tile, 8 warps x (64x32), cp.async double buf.
#define TS 4608   // floats per smem tile (128 x 36)

template <int SIDE>
__global__ __launch_bounds__(256, 2) void gemm1_tc(const float* __restrict__ bias)
{
    extern __shared__ float smx[];
    const float* A = SIDE ? g_catR : g_catL;
    float*       C = SIDE ? g_inR  : g_inL;
    const float* Bw = g_Wpad;

    int tid = threadIdx.x, l = tid & 31, w = tid >> 5;
    int wm = w & 1, wn = w >> 1;
    int m0 = blockIdx.y * 128, n0 = blockIdx.x * 128;

    float acc[4][4][4];
#pragma unroll
    for (int mi = 0; mi < 4; mi++)
#pragma unroll
        for (int nt = 0; nt < 4; nt++)
#pragma unroll
            for (int r = 0; r < 4; r++) acc[mi][nt][r] = 0.f;

    const int NS = KPAD / 32;   // 27

    // preload stage 0
    {
        float* As = smx; float* Bs = smx + TS;
#pragma unroll
        for (int r = 0; r < 4; r++) {
            int id = tid + r * 256;
            int row = id >> 3, kg = (id & 7) << 2;
            cp16(&As[row * 36 + kg], &A[(size_t)(m0 + row) * KPAD + kg]);
            cp16(&Bs[row * 36 + kg], &Bw[(size_t)(n0 + row) * KPAD + kg]);
        }
        asm volatile("cp.async.commit_group;\n");
    }

    for (int ks = 0; ks < NS; ks++) {
        if (ks + 1 < NS) {
            int k0 = (ks + 1) * 32;
            float* As = smx + ((ks + 1) & 1) * 2 * TS;
            float* Bs = As + TS;
#pragma unroll
            for (int r = 0; r < 4; r++) {
                int id = tid + r * 256;
                int row = id >> 3, kg = (id & 7) << 2;
                cp16(&As[row * 36 + kg], &A[(size_t)(m0 + row) * KPAD + k0 + kg]);
                cp16(&Bs[row * 36 + kg], &Bw[(size_t)(n0 + row) * KPAD + k0 + kg]);
            }
            asm volatile("cp.async.commit_group;\n");
            asm volatile("cp.async.wait_group 1;\n");
        } else {
            asm volatile("cp.async.wait_group 0;\n");
        }
        __syncthreads();

        float* As = smx + (ks & 1) * 2 * TS;
        float* Bs = As + TS;
#pragma unroll
        for (int ki = 0; ki < 4; ki++) {
            int kk = ki * 8;
            float4 a[4]; float2 b[4];
#pragma unroll
            for (int mi = 0; mi < 4; mi++) {
                int r0 = wm * 64 + mi * 16 + (l >> 2);
                a[mi].x = As[r0 * 36 + kk + (l & 3)];
                a[mi].y = As[(r0 + 8) * 36 + kk + (l & 3)];
                a[mi].z = As[r0 * 36 + kk + (l & 3) + 4];
                a[mi].w = As[(r0 + 8) * 36 + kk + (l & 3) + 4];
            }
#pragma unroll
            for (int nt = 0; nt < 4; nt++) {
                int c0 = wn * 32 + nt * 8 + (l >> 2);
                b[nt].x = Bs[c0 * 36 + kk + (l & 3)];
                b[nt].y = Bs[c0 * 36 + kk + (l & 3) + 4];
            }
#pragma unroll
            for (int mi = 0; mi < 4; mi++)
#pragma unroll
                for (int nt = 0; nt < 4; nt++)
                    mma_tf32(acc[mi][nt], a[mi], b[nt]);
        }
        __syncthreads();
    }

#pragma unroll
    for (int mi = 0; mi < 4; mi++) {
#pragma unroll
        for (int rh = 0; rh < 2; rh++) {
            int row = m0 + wm * 64 + mi * 16 + (l >> 2) + rh * 8;
#pragma unroll
            for (int nt = 0; nt < 4; nt++) {
                int col = n0 + wn * 32 + nt * 8 + (l & 3) * 2;
                float2 bv = *(const float2*)&bias[col];
                float2 v;
                v.x = to_tf32(tanhf(acc[mi][nt][rh * 2 + 0] + bv.x));
                v.y = to_tf32(tanhf(acc[mi][nt][rh * 2 + 1] + bv.y));
                *(float2*)&C[(size_t)row * HID + col] = v;
            }
        }
    }
}

// ---------------- 3. stage-2 tensor GEMM: xg = in @ W_ih^T + biases ----------
template <int SIDE>
__global__ __launch_bounds__(256, 2) void gemm2_tc(const float* __restrict__ b_ih,
                                                   const float* __restrict__ b_hh)
{
    extern __shared__ float smx[];
    const float* A  = SIDE ? g_inR  : g_inL;
    const float* Bw = SIDE ? g_WihR : g_WihL;
    float*       C  = SIDE ? g_xgR  : g_xgL;

    int tid = threadIdx.x, l = tid & 31, w = tid >> 5;
    int wm = w & 1, wn = w >> 1;
    int m0 = blockIdx.y * 128, n0 = blockIdx.x * 128;

    float acc[4][4][4];
#pragma unroll
    for (int mi = 0; mi < 4; mi++)
#pragma unroll
        for (int nt = 0; nt < 4; nt++)
#pragma unroll
            for (int r = 0; r < 4; r++) acc[mi][nt][r] = 0.f;

    const int NS = HID / 32;   // 16

    {
        float* As = smx; float* Bs = smx + TS;
#pragma unroll
        for (int r = 0; r < 4; r++) {
            int id = tid + r * 256;
            int row = id >> 3, kg = (id & 7) << 2;
            cp16(&As[row * 36 + kg], &A[(size_t)(m0 + row) * HID + kg]);
            cp16(&Bs[row * 36 + kg], &Bw[(size_t)(n0 + row) * HID + kg]);
        }
        asm volatile("cp.async.commit_group;\n");
    }

    for (int ks = 0; ks < NS; ks++) {
        if (ks + 1 < NS) {
            int k0 = (ks + 1) * 32;
            float* As = smx + ((ks + 1) & 1) * 2 * TS;
            float* Bs = As + TS;
#pragma unroll
            for (int r = 0; r < 4; r++) {
                int id = tid + r * 256;
                int row = id >> 3, kg = (id & 7) << 2;
                cp16(&As[row * 36 + kg], &A[(size_t)(m0 + row) * HID + k0 + kg]);
                cp16(&Bs[row * 36 + kg], &Bw[(size_t)(n0 + row) * HID + k0 + kg]);
            }
            asm volatile("cp.async.commit_group;\n");
            asm volatile("cp.async.wait_group 1;\n");
        } else {
            asm volatile("cp.async.wait_group 0;\n");
        }
        __syncthreads();

        float* As = smx + (ks & 1) * 2 * TS;
        float* Bs = As + TS;
#pragma unroll
        for (int ki = 0; ki < 4; ki++) {
            int kk = ki * 8;
            float4 a[4]; float2 b[4];
#pragma unroll
            for (int mi = 0; mi < 4; mi++) {
                int r0 = wm * 64 + mi * 16 + (l >> 2);
                a[mi].x = As[r0 * 36 + kk + (l & 3)];
                a[mi].y = As[(r0 + 8) * 36 + kk + (l & 3)];
                a[mi].z = As[r0 * 36 + kk + (l & 3) + 4];
                a[mi].w = As[(r0 + 8) * 36 + kk + (l & 3) + 4];
            }
#pragma unroll
            for (int nt = 0; nt < 4; nt++) {
                int c0 = wn * 32 + nt * 8 + (l >> 2);
                b[nt].x = Bs[c0 * 36 + kk + (l & 3)];
                b[nt].y = Bs[c0 * 36 + kk + (l & 3) + 4];
            }
#pragma unroll
            for (int mi = 0; mi < 4; mi++)
#pragma unroll
                for (int nt = 0; nt < 4; nt++)
                    mma_tf32(acc[mi][nt], a[mi], b[nt]);
        }
        __syncthreads();
    }

#pragma unroll
    for (int mi = 0; mi < 4; mi++) {
#pragma unroll
        for (int rh = 0; rh < 2; rh++) {
            int m = m0 + wm * 64 + mi * 16 + (l >> 2) + rh * 8;
            int s = m & (SS - 1);
            int b = m >> 9;
            float* crow = C + ((size_t)s * BB + b) * G4;
#pragma unroll
            for (int nt = 0; nt < 4; nt++) {
                int col = n0 + wn * 32 + nt * 8 + (l & 3) * 2;
                float2 b1 = *(const float2*)&b_ih[col];
                float2 b2 = *(const float2*)&b_hh[col];
                float2 v;
                v.x = acc[mi][nt][rh * 2 + 0] + b1.x + b2.x;
                v.y = acc[mi][nt][rh * 2 + 1] + b1.y + b2.y;
                *(float2*)&crow[col] = v;
            }
        }
    }
}

// ---------------- 4. reset LSTM state ----------------------------------------
__global__ void init_kernel()
{
    int i = blockIdx.x * blockDim.x + threadIdx.x;
    if (i == 0) { g_bar2[0] = 0u; g_bar2[1] = 0u; }
    float* h = &g_h[0][0][0];
    int n = 2 * 2 * BB * HID;
    for (int j = i; j < n; j += gridDim.x * blockDim.x) h[j] = 0.f;
}

// ---------------- 5. persistent bidirectional LSTM (tf32 tensor cores) -------
// A-fragments of h read DIRECTLY from global (L2 broadcast) — no smem staging.
#define SM_WF   0                       // 16384 floats (W fragments)
#define SM_PB   16384                   // 8448 floats  (K-partials [4][64][33])
#define SM_CST  24832                   // 512 floats   (cell state)
#define SM_TOT  25344

__global__ __launch_bounds__(256, 1) void lstm_kernel(const float* __restrict__ Whl,
                                                      const float* __restrict__ Whr,
                                                      float* __restrict__ out)
{
    extern __shared__ float sm[];
    float* Wf  = sm + SM_WF;
    float* Pb  = sm + SM_PB;
    float* Cst = sm + SM_CST;

    int tid = threadIdx.x;
    int bid = blockIdx.x;
    int dir = bid >> 6;
    int n0  = (bid & 63) << 3;

    const float* Whh = dir ? Whr : Whl;
    const float* xg  = dir ? g_xgR : g_xgL;
    float* hb0 = g_h[dir][0];
    float* hb1 = g_h[dir][1];

    // pack W slice into B-fragment layout (tf32), once
    for (int id = tid; id < 16384; id += 256) {
        int e    = id & 1;
        int lane = (id >> 1) & 31;
        int nt   = (id >> 6) & 3;
        int ki   = id >> 8;
        int k    = ki * 8 + e * 4 + (lane & 3);
        int c    = nt * 8 + (lane >> 2);
        int grow = ((c >> 3) << 9) + n0 + (c & 7);
        Wf[id] = to_tf32(Whh[(size_t)grow * 512 + k]);
    }
    for (int i = tid; i < 512; i += 256) Cst[i] = 0.f;
    __syncthreads();

    int lane = tid & 31;
    int w    = tid >> 5;
    int kq   = w >> 1;
    int mh   = w & 1;

    for (int it = 0; it < SS; it++) {
        int t = dir ? (SS - 1 - it) : it;
        const float* hprev = (it & 1) ? hb1 : hb0;
        float*       hnext = (it & 1) ? hb0 : hb1;

        float acc[2][4][4];
#pragma unroll
        for (int mi = 0; mi < 2; mi++)
#pragma unroll
            for (int nt = 0; nt < 4; nt++)
#pragma unroll
                for (int r = 0; r < 4; r++) acc[mi][nt][r] = 0.f;

#pragma unroll 4
        for (int kl = 0; kl < 16; kl++) {
            int ki = kq * 16 + kl;
            float4 a[2];
#pragma unroll
            for (int mi = 0; mi < 2; mi++) {
                int mt = mh * 2 + mi;
                a[mi] = __ldcg((const float4*)&hprev[((ki * 4 + mt) * 32 + lane) * 4]);
            }
#pragma unroll
            for (int nt = 0; nt < 4; nt++) {
                float2 b = *(const float2*)&Wf[((ki * 4 + nt) * 32 + lane) * 2];
#pragma unroll
                for (int mi = 0; mi < 2; mi++)
                    mma_tf32(acc[mi][nt], a[mi], b);
            }
        }

        // store K-partials to SMEM
#pragma unroll
        for (int mi = 0; mi < 2; mi++) {
            int mt = mh * 2 + mi;
#pragma unroll
            for (int nt = 0; nt < 4; nt++) {
#pragma unroll
                for (int r = 0; r < 4; r++) {
                    int row = mt * 16 + (lane >> 2) + ((r >> 1) << 3);
                    int col = nt * 8 + (lane & 3) * 2 + (r & 1);
                    Pb[(kq * 64 + row) * 33 + col] = acc[mi][nt][r];
                }
            }
        }
        __syncthreads();

        // gate reduction + elementwise LSTM update
        size_t xb = (size_t)t * (BB * G4);
        for (int item = tid; item < 512; item += 256) {
            int m = item >> 3, j = item & 7;
            const float* xr = xg + xb + m * G4 + n0 + j;
            float gi = xr[0],    gf = xr[512];
            float gg = xr[1024], go = xr[1536];
#pragma unroll
            for (int q = 0; q < 4; q++) {
                const float* p = &Pb[(q * 64 + m) * 33];
                gi += p[j];      gf += p[8 + j];
                gg += p[16 + j]; go += p[24 + j];
            }
            float co = Cst[item];
            float cn = sigf(gf) * co + sigf(gi) * tanhf(gg);
            float h  = sigf(go) * tanhf(cn);
            Cst[item] = cn;

            int kglob = n0 + j;
            int ki2 = kglob >> 3, kc = kglob & 7;
            int mt2 = m >> 4, mr = m & 15;
            int ln  = (mr & 7) * 4 + (kc & 3);
            int e   = ((mr >> 3) & 1) + 2 * ((kc >> 2) & 1);
            hnext[((ki2 * 4 + mt2) * 32 + ln) * 4 + e] = to_tf32(h);

            out[((size_t)m * SS + t) * 1024 + (dir << 9) + n0 + j] = h;
        }

        // per-direction grid barrier
        if (it != SS - 1) {
            __syncthreads();
            __threadfence();
            if (tid == 0) {
                atomicAdd(&g_bar2[dir], 1u);
                unsigned tgt = (unsigned)(it + 1) * 64u;
                while (*(volatile unsigned*)&g_bar2[dir] < tgt) __nanosleep(32);
            }
            __syncthreads();
        }
    }
}

// ---------------- host launch -------------------------------------------------
extern "C" void kernel_launch(void* const* d_in, const int* in_sizes, int n_in,
                              void* d_out, int out_size)
{
    const int*   char_idx  = (const int*)d_in[0];
    const int*   ctype_idx = (const int*)d_in[1];
    const int*   lbi_idx   = (const int*)d_in[2];
    const int*   rbi_idx   = (const int*)d_in[3];
    const int*   ext_idx   = (const int*)d_in[4];
    const int*   lext_idx  = (const int*)d_in[5];
    const int*   rext_idx  = (const int*)d_in[6];
    const float* charEmb   = (const float*)d_in[7];
    const float* ctypeEmb  = (const float*)d_in[8];
    const float* biEmb     = (const float*)d_in[9];
    const float* extEmb    = (const float*)d_in[10];
    const float* extBiEmb  = (const float*)d_in[11];
    const float* W_lin     = (const float*)d_in[12];
    const float* b_lin     = (const float*)d_in[13];
    const float* W_ih_l    = (const float*)d_in[14];
    const float* W_hh_l    = (const float*)d_in[15];
    const float* b_ih_l    = (const float*)d_in[16];
    const float* b_hh_l    = (const float*)d_in[17];
    const float* W_ih_r    = (const float*)d_in[18];
    const float* W_hh_r    = (const float*)d_in[19];
    const float* b_ih_r    = (const float*)d_in[20];
    const float* b_hh_r    = (const float*)d_in[21];
    float* out = (float*)d_out;

    gather_kernel<<<MTOT, 128>>>(char_idx, ctype_idx, lbi_idx, rbi_idx,
                                 ext_idx, lext_idx, rext_idx,
                                 charEmb, ctypeEmb, biEmb, extEmb, extBiEmb);
    prep_w_kernel<<<512, 128>>>(W_lin);
    prep_wih_kernel<<<256, 256>>>(W_ih_l, W_ih_r);

    const int gsm = 4 * TS * 4;   // 73728 B
    cudaFuncSetAttribute(gemm1_tc<0>, cudaFuncAttributeMaxDynamicSharedMemorySize, gsm);
    cudaFuncSetAttribute(gemm1_tc<1>, cudaFuncAttributeMaxDynamicSharedMemorySize, gsm);
    cudaFuncSetAttribute(gemm2_tc<0>, cudaFuncAttributeMaxDynamicSharedMemorySize, gsm);
    cudaFuncSetAttribute(gemm2_tc<1>, cudaFuncAttributeMaxDynamicSharedMemorySize, gsm);

    gemm1_tc<0><<<dim3(4, 256), 256, gsm>>>(b_lin);
    gemm1_tc<1><<<dim3(4, 256), 256, gsm>>>(b_lin);
    gemm2_tc<0><<<dim3(16, 256), 256, gsm>>>(b_ih_l, b_hh_l);
    gemm2_tc<1><<<dim3(16, 256), 256, gsm>>>(b_ih_r, b_hh_r);

    init_kernel<<<64, 256>>>();

    const int lstm_smem = SM_TOT * 4;   // 101376 B
    cudaFuncSetAttribute(lstm_kernel, cudaFuncAttributeMaxDynamicSharedMemorySize,
                         lstm_smem);
    lstm_kernel<<<128, 256, lstm_smem>>>(W_hh_l, W_hh_r, out);
}

// round 7
// speedup vs baseline: 2.8808x; 1.1772x over previous
#include <cuda_runtime.h>
#include <cuda_bf16.h>

#define BB   64
#define SS   512
#define KRAW 850
#define KPAD 864
#define HID  512
#define G4   2048
#define MTOT (BB * SS)

// ---------------- scratch (static device globals; no runtime alloc) ----------
__device__ __align__(16) float g_catL[(size_t)MTOT * KPAD];
__device__ __align__(16) float g_catR[(size_t)MTOT * KPAD];
__device__ __align__(16) float g_Wpad[(size_t)HID * KPAD];
__device__ __align__(16) float g_WihL[(size_t)G4 * HID];   // tf32-rounded W_ih
__device__ __align__(16) float g_WihR[(size_t)G4 * HID];
__device__ __align__(16) float g_inL[(size_t)MTOT * HID];
__device__ __align__(16) float g_inR[(size_t)MTOT * HID];
__device__ __align__(16) float g_xgL[(size_t)MTOT * G4];   // [S][B][2048]
__device__ __align__(16) float g_xgR[(size_t)MTOT * G4];
// h double buffer, bf16, packed in m16n8k16 A-fragment layout:
// word = ((ki*4+mt)*32+lane)*4+e, half = k&1, with ki=k>>4, mt=m>>4,
// lane=(m&7)*4+((k>>1)&3), e=((m>>3)&1)+2*((k>>3)&1)
__device__ __align__(16) __nv_bfloat16 g_hbf[2][2][BB * HID];
__device__ volatile unsigned g_flag[2][64];   // per-CTA step flags

__device__ __forceinline__ float sigf(float x) { return 1.f / (1.f + __expf(-x)); }
__device__ __forceinline__ float to_tf32(float x) {
    float r;
    asm("cvt.rna.tf32.f32 %0, %1;" : "=f"(r) : "f"(x));
    return r;
}
__device__ __forceinline__ float4 t4(float4 v) {
    v.x = to_tf32(v.x); v.y = to_tf32(v.y);
    v.z = to_tf32(v.z); v.w = to_tf32(v.w);
    return v;
}
__device__ __forceinline__ void mma_tf32(float* c, const float4& a, const float2& b) {
    asm volatile(
        "mma.sync.aligned.m16n8k8.row.col.f32.tf32.tf32.f32 "
        "{%0,%1,%2,%3}, {%4,%5,%6,%7}, {%8,%9}, {%0,%1,%2,%3};"
        : "+f"(c[0]), "+f"(c[1]), "+f"(c[2]), "+f"(c[3])
        : "r"(__float_as_uint(a.x)), "r"(__float_as_uint(a.y)),
          "r"(__float_as_uint(a.z)), "r"(__float_as_uint(a.w)),
          "r"(__float_as_uint(b.x)), "r"(__float_as_uint(b.y)));
}
__device__ __forceinline__ void mma_bf16(float* c, const uint4& a, const uint2& b) {
    asm volatile(
        "mma.sync.aligned.m16n8k16.row.col.f32.bf16.bf16.f32 "
        "{%0,%1,%2,%3}, {%4,%5,%6,%7}, {%8,%9}, {%0,%1,%2,%3};"
        : "+f"(c[0]), "+f"(c[1]), "+f"(c[2]), "+f"(c[3])
        : "r"(a.x), "r"(a.y), "r"(a.z), "r"(a.w), "r"(b.x), "r"(b.y));
}
__device__ __forceinline__ void cp16(void* smem, const void* gmem) {
    unsigned s = (unsigned)__cvta_generic_to_shared(smem);
    asm volatile("cp.async.cg.shared.global [%0], [%1], 16;\n" :: "r"(s), "l"(gmem));
}

// ---------------- 1. gather + concat (padded, tf32-rounded) ------------------
__global__ void gather_kernel(const int* __restrict__ char_idx,
                              const int* __restrict__ ctype_idx,
                              const int* __restrict__ lbi_idx,
                              const int* __restrict__ rbi_idx,
                              const int* __restrict__ ext_idx,
                              const int* __restrict__ lext_idx,
                              const int* __restrict__ rext_idx,
                              const float* __restrict__ charEmb,
                              const float* __restrict__ ctypeEmb,
                              const float* __restrict__ biEmb,
                              const float* __restrict__ extEmb,
                              const float* __restrict__ extBiEmb)
{
    int t = blockIdx.x;
    int tid = threadIdx.x;             // 128 threads
    float* L = g_catL + (size_t)t * KPAD;
    float* R = g_catR + (size_t)t * KPAD;

    int ci = char_idx[t];
    int ct = ctype_idx[t];
    int lb = lbi_idx[t];
    int rb = rbi_idx[t];
    int ec = ext_idx[t];
    int le = lext_idx[t];
    int re = rext_idx[t];

    const float4* c4  = (const float4*)(charEmb  + (size_t)ci * 200);
    const float4* e4  = (const float4*)(extEmb   + (size_t)ec * 200);
    const float4* lb4 = (const float4*)(biEmb    + (size_t)lb * 200);
    const float4* rb4 = (const float4*)(biEmb    + (size_t)rb * 200);
    const float4* le4 = (const float4*)(extBiEmb + (size_t)le * 200);
    const float4* re4 = (const float4*)(extBiEmb + (size_t)re * 200);

    for (int i = tid; i < 50; i += 128) {
        float4 v = t4(c4[i]);
        ((float4*)L)[i] = v;           ((float4*)R)[i] = v;
        v = t4(e4[i]);
        ((float4*)(L + 200))[i] = v;   ((float4*)(R + 200))[i] = v;
        ((float4*)(L + 400))[i] = t4(lb4[i]);
        ((float4*)(R + 400))[i] = t4(rb4[i]);
        ((float4*)(L + 600))[i] = t4(le4[i]);
        ((float4*)(R + 600))[i] = t4(re4[i]);
    }
    const float* cty = ctypeEmb + (size_t)ct * 50;
    for (int i = tid; i < KPAD - 800; i += 128) {
        float v = (i < 50) ? to_tf32(cty[i]) : 0.f;
        L[800 + i] = v;
        R[800 + i] = v;
    }
}

// ---------------- 1b. weight prep (pad + tf32 round) -------------------------
__global__ void prep_w_kernel(const float* __restrict__ W_lin)
{
    int n = blockIdx.x;
    const float* src = W_lin + (size_t)n * KRAW;
    float* dst = g_Wpad + (size_t)n * KPAD;
    for (int i = threadIdx.x; i < KPAD; i += blockDim.x)
        dst[i] = (i < KRAW) ? to_tf32(src[i]) : 0.f;
}

__global__ void prep_wih_kernel(const float* __restrict__ Wl,
                                const float* __restrict__ Wr)
{
    int i = blockIdx.x * blockDim.x + threadIdx.x;
    int n = G4 * HID;
    for (int j = i; j < n; j += gridDim.x * blockDim.x) {
        g_WihL[j] = to_tf32(Wl[j]);
        g_WihR[j] = to_tf32(Wr[j]);
    }
}

// ---------------- 2. stage-1 tensor GEMM: tanh(cat @ W_lin^T + b) ------------
#define TS 4608   // floats per smem tile (128 x 36)

template <int SIDE>
__global__ __launch_bounds__(256, 2) void gemm1_tc(const float* __restrict__ bias)
{
    extern __shared__ float smx[];
    const float* A = SIDE ? g_catR : g_catL;
    float*       C = SIDE ? g_inR  : g_inL;
    const float* Bw = g_Wpad;

    int tid = threadIdx.x, l = tid & 31, w = tid >> 5;
    int wm = w & 1, wn = w >> 1;
    int m0 = blockIdx.y * 128, n0 = blockIdx.x * 128;

    float acc[4][4][4];
#pragma unroll
    for (int mi = 0; mi < 4; mi++)
#pragma unroll
        for (int nt = 0; nt < 4; nt++)
#pragma unroll
            for (int r = 0; r < 4; r++) acc[mi][nt][r] = 0.f;

    const int NS = KPAD / 32;   // 27

    {
        float* As = smx; float* Bs = smx + TS;
#pragma unroll
        for (int r = 0; r < 4; r++) {
            int id = tid + r * 256;
            int row = id >> 3, kg = (id & 7) << 2;
            cp16(&As[row * 36 + kg], &A[(size_t)(m0 + row) * KPAD + kg]);
            cp16(&Bs[row * 36 + kg], &Bw[(size_t)(n0 + row) * KPAD + kg]);
        }
        asm volatile("cp.async.commit_group;\n");
    }

    for (int ks = 0; ks < NS; ks++) {
        if (ks + 1 < NS) {
            int k0 = (ks + 1) * 32;
            float* As = smx + ((ks + 1) & 1) * 2 * TS;
            float* Bs = As + TS;
#pragma unroll
            for (int r = 0; r < 4; r++) {
                int id = tid + r * 256;
                int row = id >> 3, kg = (id & 7) << 2;
                cp16(&As[row * 36 + kg], &A[(size_t)(m0 + row) * KPAD + k0 + kg]);
                cp16(&Bs[row * 36 + kg], &Bw[(size_t)(n0 + row) * KPAD + k0 + kg]);
            }
            asm volatile("cp.async.commit_group;\n");
            asm volatile("cp.async.wait_group 1;\n");
        } else {
            asm volatile("cp.async.wait_group 0;\n");
        }
        __syncthreads();

        float* As = smx + (ks & 1) * 2 * TS;
        float* Bs = As + TS;
#pragma unroll
        for (int ki = 0; ki < 4; ki++) {
            int kk = ki * 8;
            float4 a[4]; float2 b[4];
#pragma unroll
            for (int mi = 0; mi < 4; mi++) {
                int r0 = wm * 64 + mi * 16 + (l >> 2);
                a[mi].x = As[r0 * 36 + kk + (l & 3)];
                a[mi].y = As[(r0 + 8) * 36 + kk + (l & 3)];
                a[mi].z = As[r0 * 36 + kk + (l & 3) + 4];
                a[mi].w = As[(r0 + 8) * 36 + kk + (l & 3) + 4];
            }
#pragma unroll
            for (int nt = 0; nt < 4; nt++) {
                int c0 = wn * 32 + nt * 8 + (l >> 2);
                b[nt].x = Bs[c0 * 36 + kk + (l & 3)];
                b[nt].y = Bs[c0 * 36 + kk + (l & 3) + 4];
            }
#pragma unroll
            for (int mi = 0; mi < 4; mi++)
#pragma unroll
                for (int nt = 0; nt < 4; nt++)
                    mma_tf32(acc[mi][nt], a[mi], b[nt]);
        }
        __syncthreads();
    }

#pragma unroll
    for (int mi = 0; mi < 4; mi++) {
#pragma unroll
        for (int rh = 0; rh < 2; rh++) {
            int row = m0 + wm * 64 + mi * 16 + (l >> 2) + rh * 8;
#pragma unroll
            for (int nt = 0; nt < 4; nt++) {
                int col = n0 + wn * 32 + nt * 8 + (l & 3) * 2;
                float2 bv = *(const float2*)&bias[col];
                float2 v;
                v.x = to_tf32(tanhf(acc[mi][nt][rh * 2 + 0] + bv.x));
                v.y = to_tf32(tanhf(acc[mi][nt][rh * 2 + 1] + bv.y));
                *(float2*)&C[(size_t)row * HID + col] = v;
            }
        }
    }
}

// ---------------- 3. stage-2 tensor GEMM: xg = in @ W_ih^T + biases ----------
template <int SIDE>
__global__ __launch_bounds__(256, 2) void gemm2_tc(const float* __restrict__ b_ih,
                                                   const float* __restrict__ b_hh)
{
    extern __shared__ float smx[];
    const float* A  = SIDE ? g_inR  : g_inL;
    const float* Bw = SIDE ? g_WihR : g_WihL;
    float*       C  = SIDE ? g_xgR  : g_xgL;

    int tid = threadIdx.x, l = tid & 31, w = tid >> 5;
    int wm = w & 1, wn = w >> 1;
    int m0 = blockIdx.y * 128, n0 = blockIdx.x * 128;

    float acc[4][4][4];
#pragma unroll
    for (int mi = 0; mi < 4; mi++)
#pragma unroll
        for (int nt = 0; nt < 4; nt++)
#pragma unroll
            for (int r = 0; r < 4; r++) acc[mi][nt][r] = 0.f;

    const int NS = HID / 32;   // 16

    {
        float* As = smx; float* Bs = smx + TS;
#pragma unroll
        for (int r = 0; r < 4; r++) {
            int id = tid + r * 256;
            int row = id >> 3, kg = (id & 7) << 2;
            cp16(&As[row * 36 + kg], &A[(size_t)(m0 + row) * HID + kg]);
            cp16(&Bs[row * 36 + kg], &Bw[(size_t)(n0 + row) * HID + kg]);
        }
        asm volatile("cp.async.commit_group;\n");
    }

    for (int ks = 0; ks < NS; ks++) {
        if (ks + 1 < NS) {
            int k0 = (ks + 1) * 32;
            float* As = smx + ((ks + 1) & 1) * 2 * TS;
            float* Bs = As + TS;
#pragma unroll
            for (int r = 0; r < 4; r++) {
                int id = tid + r * 256;
                int row = id >> 3, kg = (id & 7) << 2;
                cp16(&As[row * 36 + kg], &A[(size_t)(m0 + row) * HID + k0 + kg]);
                cp16(&Bs[row * 36 + kg], &Bw[(size_t)(n0 + row) * HID + k0 + kg]);
            }
            asm volatile("cp.async.commit_group;\n");
            asm volatile("cp.async.wait_group 1;\n");
        } else {
            asm volatile("cp.async.wait_group 0;\n");
        }
        __syncthreads();

        float* As = smx + (ks & 1) * 2 * TS;
        float* Bs = As + TS;
#pragma unroll
        for (int ki = 0; ki < 4; ki++) {
            int kk = ki * 8;
            float4 a[4]; float2 b[4];
#pragma unroll
            for (int mi = 0; mi < 4; mi++) {
                int r0 = wm * 64 + mi * 16 + (l >> 2);
                a[mi].x = As[r0 * 36 + kk + (l & 3)];
                a[mi].y = As[(r0 + 8) * 36 + kk + (l & 3)];
                a[mi].z = As[r0 * 36 + kk + (l & 3) + 4];
                a[mi].w = As[(r0 + 8) * 36 + kk + (l & 3) + 4];
            }
#pragma unroll
            for (int nt = 0; nt < 4; nt++) {
                int c0 = wn * 32 + nt * 8 + (l >> 2);
                b[nt].x = Bs[c0 * 36 + kk + (l & 3)];
                b[nt].y = Bs[c0 * 36 + kk + (l & 3) + 4];
            }
#pragma unroll
            for (int mi = 0; mi < 4; mi++)
#pragma unroll
                for (int nt = 0; nt < 4; nt++)
                    mma_tf32(acc[mi][nt], a[mi], b[nt]);
        }
        __syncthreads();
    }

#pragma unroll
    for (int mi = 0; mi < 4; mi++) {
#pragma unroll
        for (int rh = 0; rh < 2; rh++) {
            int m = m0 + wm * 64 + mi * 16 + (l >> 2) + rh * 8;
            int s = m & (SS - 1);
            int b = m >> 9;
            float* crow = C + ((size_t)s * BB + b) * G4;
#pragma unroll
            for (int nt = 0; nt < 4; nt++) {
                int col = n0 + wn * 32 + nt * 8 + (l & 3) * 2;
                float2 b1 = *(const float2*)&b_ih[col];
                float2 b2 = *(const float2*)&b_hh[col];
                float2 v;
                v.x = acc[mi][nt][rh * 2 + 0] + b1.x + b2.x;
                v.y = acc[mi][nt][rh * 2 + 1] + b1.y + b2.y;
                *(float2*)&crow[col] = v;
            }
        }
    }
}

// ---------------- 4. reset LSTM state ----------------------------------------
__global__ void init_kernel()
{
    int i = blockIdx.x * blockDim.x + threadIdx.x;
    if (i < 64) { g_flag[0][i] = 0u; g_flag[1][i] = 0u; }
    unsigned* h = (unsigned*)&g_hbf[0][0][0];
    int n = 2 * 2 * BB * HID / 2;     // u32 words
    for (int j = i; j < n; j += gridDim.x * blockDim.x) h[j] = 0u;
}

// ---------------- 5. persistent bidirectional LSTM (bf16 tensor cores) -------
// SMEM bytes: Wh bf16 32768 | Pb f32 33792 | Xs f32 8192 | Cst f32 2048
#define SMB_WH   0
#define SMB_PB   32768
#define SMB_XS   66560
#define SMB_CST  74752
#define SMB_TOT  76800

__global__ __launch_bounds__(256, 1) void lstm_kernel(const float* __restrict__ Whl,
                                                      const float* __restrict__ Whr,
                                                      float* __restrict__ out)
{
    extern __shared__ char smraw[];
    __nv_bfloat16* Wh = (__nv_bfloat16*)(smraw + SMB_WH);
    unsigned* Wh32    = (unsigned*)(smraw + SMB_WH);
    float* Pb  = (float*)(smraw + SMB_PB);
    float* Xs  = (float*)(smraw + SMB_XS);
    float* Cst = (float*)(smraw + SMB_CST);

    int tid = threadIdx.x;
    int bid = blockIdx.x;
    int dir = bid >> 6;
    int slot = bid & 63;
    int n0  = slot << 3;

    const float* Whh = dir ? Whr : Whl;
    const float* xg  = dir ? g_xgR : g_xgL;
    __nv_bfloat16* hb0 = g_hbf[dir][0];
    __nv_bfloat16* hb1 = g_hbf[dir][1];

    // pack W slice into m16n8k16 B-fragment layout (bf16), once
    // id over 16384 halves: half=id&1, e=(id>>1)&1, lane=(id>>2)&31,
    // nt=(id>>7)&3, ki=id>>9 ; k=ki*16+e*8+(lane&3)*2+half ; c=nt*8+(lane>>2)
    for (int id = tid; id < 16384; id += 256) {
        int half = id & 1;
        int e    = (id >> 1) & 1;
        int lane = (id >> 2) & 31;
        int nt   = (id >> 7) & 3;
        int ki   = id >> 9;
        int k    = ki * 16 + e * 8 + (lane & 3) * 2 + half;
        int c    = nt * 8 + (lane >> 2);
        int grow = ((c >> 3) << 9) + n0 + (c & 7);
        Wh[id] = __float2bfloat16_rn(Whh[(size_t)grow * 512 + k]);
    }
    for (int i = tid; i < 512; i += 256) Cst[i] = 0.f;
    __syncthreads();

    int lane = tid & 31;
    int w    = tid >> 5;
    int kq   = w >> 1;                 // ki range [kq*8, kq*8+8)
    int mh   = w & 1;

    for (int it = 0; it < SS; it++) {
        int t = dir ? (SS - 1 - it) : it;
        const unsigned* hprev32 = (const unsigned*)((it & 1) ? hb1 : hb0);
        __nv_bfloat16*  hnext   = (it & 1) ? hb0 : hb1;

        // ---- prefetch this step's xg rows into SMEM (overlaps mma phase) ----
        size_t xb = (size_t)t * (BB * G4);
        for (int r = 0; r < 2; r++) {
            int id = tid + r * 256;    // 512 cp16: m(64) x seg(4) x q(2)
            int m = id >> 3, seg = (id >> 1) & 3, q = id & 1;
            cp16(&Xs[(m * 4 + seg) * 8 + q * 4],
                 &xg[xb + (size_t)m * G4 + n0 + seg * 512 + q * 4]);
        }
        asm volatile("cp.async.commit_group;\n");

        // ---- bf16 mma phase: A-fragments straight from L2 -------------------
        float acc[2][4][4];
#pragma unroll
        for (int mi = 0; mi < 2; mi++)
#pragma unroll
            for (int nt = 0; nt < 4; nt++)
#pragma unroll
                for (int r = 0; r < 4; r++) acc[mi][nt][r] = 0.f;

#pragma unroll
        for (int kl = 0; kl < 8; kl++) {
            int ki = kq * 8 + kl;
            uint4 a[2];
#pragma unroll
            for (int mi = 0; mi < 2; mi++) {
                int mt = mh * 2 + mi;
                a[mi] = __ldcg((const uint4*)&hprev32[((ki * 4 + mt) * 32 + lane) * 4]);
            }
#pragma unroll
            for (int nt = 0; nt < 4; nt++) {
                uint2 b = *(const uint2*)&Wh32[((ki * 4 + nt) * 32 + lane) * 2];
#pragma unroll
                for (int mi = 0; mi < 2; mi++)
                    mma_bf16(acc[mi][nt], a[mi], b);
            }
        }

        // ---- store K-partials to SMEM ---------------------------------------
#pragma unroll
        for (int mi = 0; mi < 2; mi++) {
            int mt = mh * 2 + mi;
#pragma unroll
            for (int nt = 0; nt < 4; nt++) {
#pragma unroll
                for (int r = 0; r < 4; r++) {
                    int row = mt * 16 + (lane >> 2) + ((r >> 1) << 3);
                    int col = nt * 8 + (lane & 3) * 2 + (r & 1);
                    Pb[(kq * 64 + row) * 33 + col] = acc[mi][nt][r];
                }
            }
        }
        asm volatile("cp.async.wait_group 0;\n");
        __syncthreads();

        // ---- gate reduction + elementwise LSTM update -----------------------
        for (int item = tid; item < 512; item += 256) {
            int m = item >> 3, j = item & 7;
            const float* xr = &Xs[m * 32];
            float gi = xr[j],      gf = xr[8 + j];
            float gg = xr[16 + j], go = xr[24 + j];
#pragma unroll
            for (int q = 0; q < 4; q++) {
                const float* p = &Pb[(q * 64 + m) * 33];
                gi += p[j];      gf += p[8 + j];
                gg += p[16 + j]; go += p[24 + j];
            }
            float co = Cst[item];
            float cn = sigf(gf) * co + sigf(gi) * tanhf(gg);
            float h  = sigf(go) * tanhf(cn);
            Cst[item] = cn;

            // write h (bf16) into A-fragment-packed global layout
            int kglob = n0 + j;
            int ki2 = kglob >> 4;
            int mt2 = m >> 4;
            int ln  = (m & 7) * 4 + ((kglob >> 1) & 3);
            int e   = ((m >> 3) & 1) + 2 * ((kglob >> 3) & 1);
            int word = ((ki2 * 4 + mt2) * 32 + ln) * 4 + e;
            hnext[word * 2 + (kglob & 1)] = __float2bfloat16_rn(h);

            out[((size_t)m * SS + t) * 1024 + (dir << 9) + n0 + j] = h;
        }

        // ---- flag-array grid barrier (per direction) ------------------------
        if (it != SS - 1) {
            __syncthreads();
            if (tid == 0) {
                __threadfence();
                g_flag[dir][slot] = (unsigned)(it + 1);
            }
            if (tid < 64) {
                unsigned tgt = (unsigned)(it + 1);
                while (g_flag[dir][tid] < tgt) { }
            }
            __syncthreads();
        }
    }
}

// ---------------- host launch -------------------------------------------------
extern "C" void kernel_launch(void* const* d_in, const int* in_sizes, int n_in,
                              void* d_out, int out_size)
{
    const int*   char_idx  = (const int*)d_in[0];
    const int*   ctype_idx = (const int*)d_in[1];
    const int*   lbi_idx   = (const int*)d_in[2];
    const int*   rbi_idx   = (const int*)d_in[3];
    const int*   ext_idx   = (const int*)d_in[4];
    const int*   lext_idx  = (const int*)d_in[5];
    const int*   rext_idx  = (const int*)d_in[6];
    const float* charEmb   = (const float*)d_in[7];
    const float* ctypeEmb  = (const float*)d_in[8];
    const float* biEmb     = (const float*)d_in[9];
    const float* extEmb    = (const float*)d_in[10];
    const float* extBiEmb  = (const float*)d_in[11];
    const float* W_lin     = (const float*)d_in[12];
    const float* b_lin     = (const float*)d_in[13];
    const float* W_ih_l    = (const float*)d_in[14];
    const float* W_hh_l    = (const float*)d_in[15];
    const float* b_ih_l    = (const float*)d_in[16];
    const float* b_hh_l    = (const float*)d_in[17];
    const float* W_ih_r    = (const float*)d_in[18];
    const float* W_hh_r    = (const float*)d_in[19];
    const float* b_ih_r    = (const float*)d_in[20];
    const float* b_hh_r    = (const float*)d_in[21];
    float* out = (float*)d_out;

    gather_kernel<<<MTOT, 128>>>(char_idx, ctype_idx, lbi_idx, rbi_idx,
                                 ext_idx, lext_idx, rext_idx,
                                 charEmb, ctypeEmb, biEmb, extEmb, extBiEmb);
    prep_w_kernel<<<512, 128>>>(W_lin);
    prep_wih_kernel<<<256, 256>>>(W_ih_l, W_ih_r);

    const int gsm = 4 * TS * 4;   // 73728 B
    cudaFuncSetAttribute(gemm1_tc<0>, cudaFuncAttributeMaxDynamicSharedMemorySize, gsm);
    cudaFuncSetAttribute(gemm1_tc<1>, cudaFuncAttributeMaxDynamicSharedMemorySize, gsm);
    cudaFuncSetAttribute(gemm2_tc<0>, cudaFuncAttributeMaxDynamicSharedMemorySize, gsm);
    cudaFuncSetAttribute(gemm2_tc<1>, cudaFuncAttributeMaxDynamicSharedMemorySize, gsm);

    gemm1_tc<0><<<dim3(4, 256), 256, gsm>>>(b_lin);
    gemm1_tc<1><<<dim3(4, 256), 256, gsm>>>(b_lin);
    gemm2_tc<0><<<dim3(16, 256), 256, gsm>>>(b_ih_l, b_hh_l);
    gemm2_tc<1><<<dim3(16, 256), 256, gsm>>>(b_ih_r, b_hh_r);

    init_kernel<<<64, 256>>>();

    cudaFuncSetAttribute(lstm_kernel, cudaFuncAttributeMaxDynamicSharedMemorySize,
                         SMB_TOT);
    lstm_kernel<<<128, 256, SMB_TOT>>>(W_hh_l, W_hh_r, out);
}

// round 8
// speedup vs baseline: 4.1943x; 1.4559x over previous
#include <cuda_runtime.h>
#include <cuda_bf16.h>

#define BB   64
#define SS   512
#define KRAW 850
#define KPAD 864
#define HID  512
#define G4   2048
#define MTOT (BB * SS)

// ---------------- scratch (static device globals; no runtime alloc) ----------
__device__ __align__(16) float g_catL[(size_t)MTOT * KPAD];
__device__ __align__(16) float g_catR[(size_t)MTOT * KPAD];
__device__ __align__(16) float g_Wpad[(size_t)HID * KPAD];
__device__ __align__(16) float g_WihL[(size_t)G4 * HID];
__device__ __align__(16) float g_WihR[(size_t)G4 * HID];
__device__ __align__(16) float g_inL[(size_t)MTOT * HID];
__device__ __align__(16) float g_inR[(size_t)MTOT * HID];
__device__ __align__(16) float g_xgL[(size_t)MTOT * G4];   // [S][B][2048]
__device__ __align__(16) float g_xgR[(size_t)MTOT * G4];
// h double buffer, bf16, m16n8k16 A-fragment packed (see lstm_kernel)
__device__ __align__(16) __nv_bfloat16 g_hbf[2][2][BB * HID];
__device__ unsigned g_cnt[2];                  // per-direction step counter

__device__ __forceinline__ float sigf(float x) { return 1.f / (1.f + __expf(-x)); }
__device__ __forceinline__ float tanhfast(float x) {
    float e = __expf(2.f * x);
    return (e - 1.f) * __frcp_rn(e + 1.f);
}
__device__ __forceinline__ float to_tf32(float x) {
    float r;
    asm("cvt.rna.tf32.f32 %0, %1;" : "=f"(r) : "f"(x));
    return r;
}
__device__ __forceinline__ float4 t4(float4 v) {
    v.x = to_tf32(v.x); v.y = to_tf32(v.y);
    v.z = to_tf32(v.z); v.w = to_tf32(v.w);
    return v;
}
__device__ __forceinline__ void mma_tf32(float* c, const uint4& a, unsigned b0, unsigned b1) {
    asm volatile(
        "mma.sync.aligned.m16n8k8.row.col.f32.tf32.tf32.f32 "
        "{%0,%1,%2,%3}, {%4,%5,%6,%7}, {%8,%9}, {%0,%1,%2,%3};"
        : "+f"(c[0]), "+f"(c[1]), "+f"(c[2]), "+f"(c[3])
        : "r"(a.x), "r"(a.y), "r"(a.z), "r"(a.w), "r"(b0), "r"(b1));
}
__device__ __forceinline__ void mma_bf16(float* c, const uint4& a, const uint2& b) {
    asm volatile(
        "mma.sync.aligned.m16n8k16.row.col.f32.bf16.bf16.f32 "
        "{%0,%1,%2,%3}, {%4,%5,%6,%7}, {%8,%9}, {%0,%1,%2,%3};"
        : "+f"(c[0]), "+f"(c[1]), "+f"(c[2]), "+f"(c[3])
        : "r"(a.x), "r"(a.y), "r"(a.z), "r"(a.w), "r"(b.x), "r"(b.y));
}
__device__ __forceinline__ void ldsm4(uint4& d, const float* p) {
    unsigned a = (unsigned)__cvta_generic_to_shared(p);
    asm volatile("ldmatrix.sync.aligned.m8n8.x4.shared.b16 {%0,%1,%2,%3}, [%4];"
                 : "=r"(d.x), "=r"(d.y), "=r"(d.z), "=r"(d.w) : "r"(a));
}
__device__ __forceinline__ void cp16(void* smem, const void* gmem) {
    unsigned s = (unsigned)__cvta_generic_to_shared(smem);
    asm volatile("cp.async.cg.shared.global [%0], [%1], 16;\n" :: "r"(s), "l"(gmem));
}

// ---------------- 1. gather + concat (padded, tf32-rounded) ------------------
__global__ void gather_kernel(const int* __restrict__ char_idx,
                              const int* __restrict__ ctype_idx,
                              const int* __restrict__ lbi_idx,
                              const int* __restrict__ rbi_idx,
                              const int* __restrict__ ext_idx,
                              const int* __restrict__ lext_idx,
                              const int* __restrict__ rext_idx,
                              const float* __restrict__ charEmb,
                              const float* __restrict__ ctypeEmb,
                              const float* __restrict__ biEmb,
                              const float* __restrict__ extEmb,
                              const float* __restrict__ extBiEmb)
{
    int t = blockIdx.x;
    int tid = threadIdx.x;             // 128 threads
    float* L = g_catL + (size_t)t * KPAD;
    float* R = g_catR + (size_t)t * KPAD;

    int ci = char_idx[t];
    int ct = ctype_idx[t];
    int lb = lbi_idx[t];
    int rb = rbi_idx[t];
    int ec = ext_idx[t];
    int le = lext_idx[t];
    int re = rext_idx[t];

    const float4* c4  = (const float4*)(charEmb  + (size_t)ci * 200);
    const float4* e4  = (const float4*)(extEmb   + (size_t)ec * 200);
    const float4* lb4 = (const float4*)(biEmb    + (size_t)lb * 200);
    const float4* rb4 = (const float4*)(biEmb    + (size_t)rb * 200);
    const float4* le4 = (const float4*)(extBiEmb + (size_t)le * 200);
    const float4* re4 = (const float4*)(extBiEmb + (size_t)re * 200);

    for (int i = tid; i < 50; i += 128) {
        float4 v = t4(c4[i]);
        ((float4*)L)[i] = v;           ((float4*)R)[i] = v;
        v = t4(e4[i]);
        ((float4*)(L + 200))[i] = v;   ((float4*)(R + 200))[i] = v;
        ((float4*)(L + 400))[i] = t4(lb4[i]);
        ((float4*)(R + 400))[i] = t4(rb4[i]);
        ((float4*)(L + 600))[i] = t4(le4[i]);
        ((float4*)(R + 600))[i] = t4(re4[i]);
    }
    const float* cty = ctypeEmb + (size_t)ct * 50;
    for (int i = tid; i < KPAD - 800; i += 128) {
        float v = (i < 50) ? to_tf32(cty[i]) : 0.f;
        L[800 + i] = v;
        R[800 + i] = v;
    }
}

// ---------------- 1b. weight prep (pad + tf32 round) -------------------------
__global__ void prep_w_kernel(const float* __restrict__ W_lin)
{
    int n = blockIdx.x;
    const float* src = W_lin + (size_t)n * KRAW;
    float* dst = g_Wpad + (size_t)n * KPAD;
    for (int i = threadIdx.x; i < KPAD; i += blockDim.x)
        dst[i] = (i < KRAW) ? to_tf32(src[i]) : 0.f;
}

__global__ void prep_wih_kernel(const float* __restrict__ Wl,
                                const float* __restrict__ Wr)
{
    int i = blockIdx.x * blockDim.x + threadIdx.x;
    int n = G4 * HID;
    for (int j = i; j < n; j += gridDim.x * blockDim.x) {
        g_WihL[j] = to_tf32(Wl[j]);
        g_WihR[j] = to_tf32(Wr[j]);
    }
}

// ---------------- 2. stage-1 tensor GEMM: tanh(cat @ W_lin^T + b) ------------
#define TS 4608   // floats per smem tile (128 x 36)

template <int SIDE>
__global__ __launch_bounds__(256, 2) void gemm1_tc(const float* __restrict__ bias)
{
    extern __shared__ float smx[];
    const float* A = SIDE ? g_catR : g_catL;
    float*       C = SIDE ? g_inR  : g_inL;
    const float* Bw = g_Wpad;

    int tid = threadIdx.x, l = tid & 31, w = tid >> 5;
    int wm = w & 1, wn = w >> 1;
    int m0 = blockIdx.y * 128, n0 = blockIdx.x * 128;

    float acc[4][4][4];
#pragma unroll
    for (int mi = 0; mi < 4; mi++)
#pragma unroll
        for (int nt = 0; nt < 4; nt++)
#pragma unroll
            for (int r = 0; r < 4; r++) acc[mi][nt][r] = 0.f;

    const int NS = KPAD / 32;   // 27

    {
        float* As = smx; float* Bs = smx + TS;
#pragma unroll
        for (int r = 0; r < 4; r++) {
            int id = tid + r * 256;
            int row = id >> 3, kg = (id & 7) << 2;
            cp16(&As[row * 36 + kg], &A[(size_t)(m0 + row) * KPAD + kg]);
            cp16(&Bs[row * 36 + kg], &Bw[(size_t)(n0 + row) * KPAD + kg]);
        }
        asm volatile("cp.async.commit_group;\n");
    }

    for (int ks = 0; ks < NS; ks++) {
        if (ks + 1 < NS) {
            int k0 = (ks + 1) * 32;
            float* As = smx + ((ks + 1) & 1) * 2 * TS;
            float* Bs = As + TS;
#pragma unroll
            for (int r = 0; r < 4; r++) {
                int id = tid + r * 256;
                int row = id >> 3, kg = (id & 7) << 2;
                cp16(&As[row * 36 + kg], &A[(size_t)(m0 + row) * KPAD + k0 + kg]);
                cp16(&Bs[row * 36 + kg], &Bw[(size_t)(n0 + row) * KPAD + k0 + kg]);
            }
            asm volatile("cp.async.commit_group;\n");
            asm volatile("cp.async.wait_group 1;\n");
        } else {
            asm volatile("cp.async.wait_group 0;\n");
        }
        __syncthreads();

        float* As = smx + (ks & 1) * 2 * TS;
        float* Bs = As + TS;
        const float* Aq = &As[(wm * 64 + (l & 15)) * 36 + (l >> 4) * 4];
        const float* Bq = &Bs[(wn * 32 + l) * 36];
#pragma unroll
        for (int ki = 0; ki < 4; ki++) {
            int kk = ki * 8;
            uint4 a[4], bx, by;
#pragma unroll
            for (int mi = 0; mi < 4; mi++)
                ldsm4(a[mi], Aq + mi * 16 * 36 + kk);
            ldsm4(bx, Bq + kk);
            ldsm4(by, Bq + kk + 4);
            const unsigned* bxp = &bx.x;
            const unsigned* byp = &by.x;
#pragma unroll
            for (int mi = 0; mi < 4; mi++)
#pragma unroll
                for (int nt = 0; nt < 4; nt++)
                    mma_tf32(acc[mi][nt], a[mi], bxp[nt], byp[nt]);
        }
        __syncthreads();
    }

#pragma unroll
    for (int mi = 0; mi < 4; mi++) {
#pragma unroll
        for (int rh = 0; rh < 2; rh++) {
            int row = m0 + wm * 64 + mi * 16 + (l >> 2) + rh * 8;
#pragma unroll
            for (int nt = 0; nt < 4; nt++) {
                int col = n0 + wn * 32 + nt * 8 + (l & 3) * 2;
                float2 bv = *(const float2*)&bias[col];
                float2 v;
                v.x = to_tf32(tanhf(acc[mi][nt][rh * 2 + 0] + bv.x));
                v.y = to_tf32(tanhf(acc[mi][nt][rh * 2 + 1] + bv.y));
                *(float2*)&C[(size_t)row * HID + col] = v;
            }
        }
    }
}

// ---------------- 3. stage-2 tensor GEMM: xg = in @ W_ih^T + biases ----------
template <int SIDE>
__global__ __launch_bounds__(256, 2) void gemm2_tc(const float* __restrict__ b_ih,
                                                   const float* __restrict__ b_hh)
{
    extern __shared__ float smx[];
    const float* A  = SIDE ? g_inR  : g_inL;
    const float* Bw = SIDE ? g_WihR : g_WihL;
    float*       C  = SIDE ? g_xgR  : g_xgL;

    int tid = threadIdx.x, l = tid & 31, w = tid >> 5;
    int wm = w & 1, wn = w >> 1;
    int m0 = blockIdx.y * 128, n0 = blockIdx.x * 128;

    float acc[4][4][4];
#pragma unroll
    for (int mi = 0; mi < 4; mi++)
#pragma unroll
        for (int nt = 0; nt < 4; nt++)
#pragma unroll
            for (int r = 0; r < 4; r++) acc[mi][nt][r] = 0.f;

    const int NS = HID / 32;   // 16

    {
        float* As = smx; float* Bs = smx + TS;
#pragma unroll
        for (int r = 0; r < 4; r++) {
            int id = tid + r * 256;
            int row = id >> 3, kg = (id & 7) << 2;
            cp16(&As[row * 36 + kg], &A[(size_t)(m0 + row) * HID + kg]);
            cp16(&Bs[row * 36 + kg], &Bw[(size_t)(n0 + row) * HID + kg]);
        }
        asm volatile("cp.async.commit_group;\n");
    }

    for (int ks = 0; ks < NS; ks++) {
        if (ks + 1 < NS) {
            int k0 = (ks + 1) * 32;
            float* As = smx + ((ks + 1) & 1) * 2 * TS;
            float* Bs = As + TS;
#pragma unroll
            for (int r = 0; r < 4; r++) {
                int id = tid + r * 256;
                int row = id >> 3, kg = (id & 7) << 2;
                cp16(&As[row * 36 + kg], &A[(size_t)(m0 + row) * HID + k0 + kg]);
                cp16(&Bs[row * 36 + kg], &Bw[(size_t)(n0 + row) * HID + k0 + kg]);
            }
            asm volatile("cp.async.commit_group;\n");
            asm volatile("cp.async.wait_group 1;\n");
        } else {
            asm volatile("cp.async.wait_group 0;\n");
        }
        __syncthreads();

        float* As = smx + (ks & 1) * 2 * TS;
        float* Bs = As + TS;
        const float* Aq = &As[(wm * 64 + (l & 15)) * 36 + (l >> 4) * 4];
        const float* Bq = &Bs[(wn * 32 + l) * 36];
#pragma unroll
        for (int ki = 0; ki < 4; ki++) {
            int kk = ki * 8;
            uint4 a[4], bx, by;
#pragma unroll
            for (int mi = 0; mi < 4; mi++)
                ldsm4(a[mi], Aq + mi * 16 * 36 + kk);
            ldsm4(bx, Bq + kk);
            ldsm4(by, Bq + kk + 4);
            const unsigned* bxp = &bx.x;
            const unsigned* byp = &by.x;
#pragma unroll
            for (int mi = 0; mi < 4; mi++)
#pragma unroll
                for (int nt = 0; nt < 4; nt++)
                    mma_tf32(acc[mi][nt], a[mi], bxp[nt], byp[nt]);
        }
        __syncthreads();
    }

#pragma unroll
    for (int mi = 0; mi < 4; mi++) {
#pragma unroll
        for (int rh = 0; rh < 2; rh++) {
            int m = m0 + wm * 64 + mi * 16 + (l >> 2) + rh * 8;
            int s = m & (SS - 1);
            int b = m >> 9;
            float* crow = C + ((size_t)s * BB + b) * G4;
#pragma unroll
            for (int nt = 0; nt < 4; nt++) {
                int col = n0 + wn * 32 + nt * 8 + (l & 3) * 2;
                float2 b1 = *(const float2*)&b_ih[col];
                float2 b2 = *(const float2*)&b_hh[col];
                float2 v;
                v.x = acc[mi][nt][rh * 2 + 0] + b1.x + b2.x;
                v.y = acc[mi][nt][rh * 2 + 1] + b1.y + b2.y;
                *(float2*)&crow[col] = v;
            }
        }
    }
}

// ---------------- 4. reset LSTM state ----------------------------------------
__global__ void init_kernel()
{
    int i = blockIdx.x * blockDim.x + threadIdx.x;
    if (i < 2) g_cnt[i] = 0u;
    unsigned* h = (unsigned*)&g_hbf[0][0][0];
    int n = 2 * 2 * BB * HID / 2;
    for (int j = i; j < n; j += gridDim.x * blockDim.x) h[j] = 0u;
}

// ---------------- 5. persistent bidirectional LSTM (bf16 tensor cores) -------
// 128 CTAs: dir = bid>>6, CTA owns 8 hidden units (32 gate cols).
// Warp = (mt 0..3) x (kq 0..1); kq=1 partials exchanged via Pb; full LSTM cell
// update done in registers by kq=0 threads (c-state in registers).
// SMEM bytes: Wh bf16 32768 | Pb f32 8704 | Xs f32 2x8192
#define SMB_WH   0
#define SMB_PB   32768
#define SMB_XS   41472
#define SMB_TOT  57856

__global__ __launch_bounds__(256, 1) void lstm_kernel(const float* __restrict__ Whl,
                                                      const float* __restrict__ Whr,
                                                      float* __restrict__ out)
{
    extern __shared__ char smraw[];
    __nv_bfloat16* Wh = (__nv_bfloat16*)(smraw + SMB_WH);
    unsigned* Wh32    = (unsigned*)(smraw + SMB_WH);
    float* Pb  = (float*)(smraw + SMB_PB);
    float* Xs0 = (float*)(smraw + SMB_XS);
    float* Xs1 = (float*)(smraw + SMB_XS + 8192);

    int tid = threadIdx.x;
    int bid = blockIdx.x;
    int dir = bid >> 6;
    int n0  = (bid & 63) << 3;

    const float* Whh = dir ? Whr : Whl;
    const float* xg  = dir ? g_xgR : g_xgL;
    __nv_bfloat16* hb0 = g_hbf[dir][0];
    __nv_bfloat16* hb1 = g_hbf[dir][1];
    unsigned* cnt = &g_cnt[dir];

    // pack W slice into m16n8k16 B-fragment layout (bf16), once
    for (int id = tid; id < 16384; id += 256) {
        int half = id & 1;
        int e    = (id >> 1) & 1;
        int lane = (id >> 2) & 31;
        int nt   = (id >> 7) & 3;
        int ki   = id >> 9;
        int k    = ki * 16 + e * 8 + (lane & 3) * 2 + half;
        int c    = nt * 8 + (lane >> 2);
        int grow = ((c >> 3) << 9) + n0 + (c & 7);
        Wh[id] = __float2bfloat16_rn(Whh[(size_t)grow * 512 + k]);
    }

    int lane = tid & 31;
    int w    = tid >> 5;
    int mt   = w & 3;
    int kq   = w >> 2;                 // 0/1 : K halves

    float creg[4];                     // cell state (kq==0 threads)
#pragma unroll
    for (int r = 0; r < 4; r++) creg[r] = 0.f;

    // prefetch xg for step 0
    {
        int t0 = dir ? (SS - 1) : 0;
        size_t xb = (size_t)t0 * (BB * G4);
        for (int r = 0; r < 2; r++) {
            int id = tid + r * 256;
            int m = id >> 3, seg = (id >> 1) & 3, q = id & 1;
            cp16(&Xs0[(m * 4 + seg) * 8 + q * 4],
                 &xg[xb + (size_t)m * G4 + n0 + seg * 512 + q * 4]);
        }
        asm volatile("cp.async.commit_group;\n");
    }
    __syncthreads();

    int slot17 = (mt * 32 + lane) * 17;

    for (int it = 0; it < SS; it++) {
        int t = dir ? (SS - 1 - it) : it;
        const unsigned* hprev32 = (const unsigned*)((it & 1) ? hb1 : hb0);
        __nv_bfloat16*  hnext   = (it & 1) ? hb0 : hb1;
        float* Xc = (it & 1) ? Xs1 : Xs0;
        float* Xn = (it & 1) ? Xs0 : Xs1;

        // ---- bf16 mma: A-fragments straight from L2 -------------------------
        float acc[4][4];
#pragma unroll
        for (int nt = 0; nt < 4; nt++)
#pragma unroll
            for (int r = 0; r < 4; r++) acc[nt][r] = 0.f;

        const uint4* ap = (const uint4*)&hprev32[(((kq * 16) * 4 + mt) * 32 + lane) * 4];
#pragma unroll
        for (int kl = 0; kl < 16; kl++) {
            uint4 a = __ldcg(ap + kl * 128);       // ki stride: 4*32*4 u32 = 128 uint4
            int ki = kq * 16 + kl;
#pragma unroll
            for (int nt = 0; nt < 4; nt++) {
                uint2 b = *(const uint2*)&Wh32[((ki * 4 + nt) * 32 + lane) * 2];
                mma_bf16(acc[nt], a, b);
            }
        }

        // ---- K-partial exchange: kq=1 -> smem -------------------------------
        if (kq) {
#pragma unroll
            for (int nt = 0; nt < 4; nt++)
#pragma unroll
                for (int r = 0; r < 4; r++)
                    Pb[slot17 + nt * 4 + r] = acc[nt][r];
        }
        asm volatile("cp.async.wait_group 0;\n");
        __syncthreads();

        if (!kq) {
            // ---- full cell update in registers ------------------------------
#pragma unroll
            for (int rh = 0; rh < 2; rh++) {
                int m = mt * 16 + (lane >> 2) + rh * 8;
                const float* xr = &Xc[m * 32];
                int je = (lane & 3) * 2;           // even unit of the pair
                float hpair[2];
#pragma unroll
                for (int c = 0; c < 2; c++) {
                    int r = rh * 2 + c;
                    int j = je + c;
                    float gi = acc[0][r] + Pb[slot17 + 0 + r]  + xr[j];
                    float gf = acc[1][r] + Pb[slot17 + 4 + r]  + xr[8 + j];
                    float gg = acc[2][r] + Pb[slot17 + 8 + r]  + xr[16 + j];
                    float go = acc[3][r] + Pb[slot17 + 12 + r] + xr[24 + j];
                    float cn = sigf(gf) * creg[r] + sigf(gi) * tanhfast(gg);
                    float h  = sigf(go) * tanhfast(cn);
                    creg[r] = cn;
                    hpair[c] = h;
                }
                // packed bf16x2 h write (both halves of one word)
                int kge = n0 + je;
                int ki2 = kge >> 4;
                int ln  = (m & 7) * 4 + ((kge >> 1) & 3);
                int e   = ((m >> 3) & 1) + 2 * ((kge >> 3) & 1);
                unsigned word = (__bfloat16_as_ushort(__float2bfloat16_rn(hpair[0]))) |
                                ((unsigned)__bfloat16_as_ushort(__float2bfloat16_rn(hpair[1])) << 16);
                unsigned* dst = (unsigned*)hnext + ((ki2 * 4 + mt) * 32 + ln) * 4 + e;
                asm volatile("st.global.cg.u32 [%0], %1;" :: "l"(dst), "r"(word));
                // fp32 output write
                float2 ov; ov.x = hpair[0]; ov.y = hpair[1];
                *(float2*)&out[((size_t)m * SS + t) * 1024 + (dir << 9) + n0 + je] = ov;
            }
        }

        // ---- prefetch next step's xg (overlaps barrier wait) ----------------
        if (it + 1 < SS) {
            int tn = dir ? (SS - 2 - it) : (it + 1);
            size_t xb = (size_t)tn * (BB * G4);
            for (int r = 0; r < 2; r++) {
                int id = tid + r * 256;
                int m = id >> 3, seg = (id >> 1) & 3, q = id & 1;
                cp16(&Xn[(m * 4 + seg) * 8 + q * 4],
                     &xg[xb + (size_t)m * G4 + n0 + seg * 512 + q * 4]);
            }
            asm volatile("cp.async.commit_group;\n");

            // ---- single-counter grid barrier (per direction) ----------------
            __syncthreads();
            if (tid == 0) {
                __threadfence();
                atomicAdd(cnt, 1u);
                unsigned tgt = 64u * (unsigned)(it + 1);
                unsigned v;
                while (true) {
                    asm volatile("ld.global.cg.u32 %0, [%1];" : "=r"(v) : "l"(cnt));
                    if (v >= tgt) break;
                    __nanosleep(16);
                }
            }
            __syncthreads();
        }
    }
}

// ---------------- host launch -------------------------------------------------
extern "C" void kernel_launch(void* const* d_in, const int* in_sizes, int n_in,
                              void* d_out, int out_size)
{
    const int*   char_idx  = (const int*)d_in[0];
    const int*   ctype_idx = (const int*)d_in[1];
    const int*   lbi_idx   = (const int*)d_in[2];
    const int*   rbi_idx   = (const int*)d_in[3];
    const int*   ext_idx   = (const int*)d_in[4];
    const int*   lext_idx  = (const int*)d_in[5];
    const int*   rext_idx  = (const int*)d_in[6];
    const float* charEmb   = (const float*)d_in[7];
    const float* ctypeEmb  = (const float*)d_in[8];
    const float* biEmb     = (const float*)d_in[9];
    const float* extEmb    = (const float*)d_in[10];
    const float* extBiEmb  = (const float*)d_in[11];
    const float* W_lin     = (const float*)d_in[12];
    const float* b_lin     = (const float*)d_in[13];
    const float* W_ih_l    = (const float*)d_in[14];
    const float* W_hh_l    = (const float*)d_in[15];
    const float* b_ih_l    = (const float*)d_in[16];
    const float* b_hh_l    = (const float*)d_in[17];
    const float* W_ih_r    = (const float*)d_in[18];
    const float* W_hh_r    = (const float*)d_in[19];
    const float* b_ih_r    = (const float*)d_in[20];
    const float* b_hh_r    = (const float*)d_in[21];
    float* out = (float*)d_out;

    gather_kernel<<<MTOT, 128>>>(char_idx, ctype_idx, lbi_idx, rbi_idx,
                                 ext_idx, lext_idx, rext_idx,
                                 charEmb, ctypeEmb, biEmb, extEmb, extBiEmb);
    prep_w_kernel<<<512, 128>>>(W_lin);
    prep_wih_kernel<<<256, 256>>>(W_ih_l, W_ih_r);

    const int gsm = 4 * TS * 4;   // 73728 B
    cudaFuncSetAttribute(gemm1_tc<0>, cudaFuncAttributeMaxDynamicSharedMemorySize, gsm);
    cudaFuncSetAttribute(gemm1_tc<1>, cudaFuncAttributeMaxDynamicSharedMemorySize, gsm);
    cudaFuncSetAttribute(gemm2_tc<0>, cudaFuncAttributeMaxDynamicSharedMemorySize, gsm);
    cudaFuncSetAttribute(gemm2_tc<1>, cudaFuncAttributeMaxDynamicSharedMemorySize, gsm);

    gemm1_tc<0><<<dim3(4, 256), 256, gsm>>>(b_lin);
    gemm1_tc<1><<<dim3(4, 256), 256, gsm>>>(b_lin);
    gemm2_tc<0><<<dim3(16, 256), 256, gsm>>>(b_ih_l, b_hh_l);
    gemm2_tc<1><<<dim3(16, 256), 256, gsm>>>(b_ih_r, b_hh_r);

    init_kernel<<<64, 256>>>();

    cudaFuncSetAttribute(lstm_kernel, cudaFuncAttributeMaxDynamicSharedMemorySize,
                         SMB_TOT);
    lstm_kernel<<<128, 256, SMB_TOT>>>(W_hh_l, W_hh_r, out);
}